// round 6
// baseline (speedup 1.0000x reference)
#include <cuda_runtime.h>
#include <cstdint>
#include <math.h>

// ---------------------------------------------------------------------------
// PcLinearBlock: ARCH=(1024,2048,2048,512), BATCH=4096, STEPS=20, LR=0.1
// Inputs: x, W0, b0, W1, b1, W2, b2. Output: r3 (4096x512) + total_error.
// tf32 mma.sync (m16n8k8) GEMM, 128x128x32 tile, cp.async 3-stage pipeline.
// (tcgen05 is unavailable: harness PTX target is base sm_103, no 'a' suffix.)
// ---------------------------------------------------------------------------

#define MB 4096
#define D0 1024
#define D1 2048
#define D2 2048
#define D3 512
#define NSTEPS 20
#define LRC 0.1f

// ---- scratch (device globals; allocation-free) ----
__device__ __align__(128) float g_r1[(size_t)MB * D1];
__device__ __align__(128) float g_r2[(size_t)MB * D2];
__device__ __align__(128) float g_r3[(size_t)MB * D3];
__device__ __align__(128) float g_e0[(size_t)MB * D0];
__device__ __align__(128) float g_e1[(size_t)MB * D1];
__device__ __align__(128) float g_e2[(size_t)MB * D2];
__device__ __align__(128) float g_Wt0[(size_t)D0 * D1];
__device__ __align__(128) float g_Wt1[(size_t)D1 * D2];
__device__ __align__(128) float g_Wt2[(size_t)D2 * D3];
__device__ float g_part[4096];

// ---------------------------------------------------------------------------
// helpers
// ---------------------------------------------------------------------------
__device__ __forceinline__ uint32_t s2u(const void* p) {
    uint32_t a;
    asm("{ .reg .u64 t; cvta.to.shared.u64 t, %1; cvt.u32.u64 %0, t; }"
        : "=r"(a) : "l"(p));
    return a;
}

__device__ __forceinline__ void cp16(uint32_t dst, const void* src) {
    asm volatile("cp.async.cg.shared.global [%0], [%1], 16;"
                 :: "r"(dst), "l"(src));
}

__device__ __forceinline__ float ldsf(uint32_t addr) {
    float v;
    asm volatile("ld.shared.f32 %0, [%1];" : "=f"(v) : "r"(addr));
    return v;
}

__device__ __forceinline__ uint32_t f2tf32(float f) {
    uint32_t u;
    asm("cvt.rna.tf32.f32 %0, %1;" : "=r"(u) : "f"(f));
    return u;
}

__device__ __forceinline__ void mma8(float* c, const uint32_t* a,
                                     const uint32_t* b) {
    asm volatile(
        "mma.sync.aligned.m16n8k8.row.col.f32.tf32.tf32.f32 "
        "{%0,%1,%2,%3}, {%4,%5,%6,%7}, {%8,%9}, {%0,%1,%2,%3};"
        : "+f"(c[0]), "+f"(c[1]), "+f"(c[2]), "+f"(c[3])
        : "r"(a[0]), "r"(a[1]), "r"(a[2]), "r"(a[3]), "r"(b[0]), "r"(b[1]));
}

// exact algebraic tanh: (e^{2x}-1)/(e^{2x}+1); saturates correctly.
__device__ __forceinline__ float fast_tanh(float x) {
    float e = __expf(2.0f * x);
    return 1.0f - 2.0f / (e + 1.0f);
}

// ---------------------------------------------------------------------------
// tf32 GEMM:  C[m,n] = sum_k A[m,k] * B[n,k]   (A MxK, B NxK, both K-major)
// CTA tile 128x128x32, 256 threads (8 warps, warp tile 64x32).
// Smem stage: A 128x36 fp32 (18432 B) + B 128x36 (18432 B); 3 stages.
// EPI 0: D = tanh(acc + X[n])      (X = bias)
// EPI 1: D = X - tanh(acc)         (X = prev state, MxN)
// EPI 2: D = D + LR*(acc - X)      (X = error, MxN; in place)
// ---------------------------------------------------------------------------
#define STG_B   36864            // bytes per stage (A+B)
#define SMEM_SZ (3 * STG_B)      // 110592

template <int EPI>
__global__ void __launch_bounds__(256, 2)
tc_gemm(const float* __restrict__ A, const float* __restrict__ B,
        const float* __restrict__ X, float* __restrict__ D, int N, int K)
{
    extern __shared__ char smem[];
    const uint32_t sb = s2u(smem);
    const int tid = threadIdx.x;
    const int wid = tid >> 5, lane = tid & 31;
    const int gid = lane >> 2, tig = lane & 3;
    const int warp_m = wid & 1;       // 0..1 -> 64 rows each
    const int warp_n = wid >> 1;      // 0..3 -> 32 cols each
    const int bm = blockIdx.y * 128, bn = blockIdx.x * 128;

    // global->smem copy mapping: thread t copies 64B (4x16B) of row t/2
    const int ar = tid >> 1;
    const float* gA = A + (size_t)(bm + ar) * K + (tid & 1) * 16;
    const float* gB = B + (size_t)(bn + ar) * K + (tid & 1) * 16;
    const uint32_t soff = (uint32_t)(ar * 144 + (tid & 1) * 64);

    const int KT = K >> 5;            // 32-float K chunks

    // ---- prologue: prefetch stages 0..2
#pragma unroll
    for (int kt = 0; kt < 3; kt++) {
        uint32_t base = sb + kt * STG_B;
        const float* pa = gA + kt * 32;
        const float* pb = gB + kt * 32;
#pragma unroll
        for (int i = 0; i < 4; i++) cp16(base + soff + i * 16, pa + i * 4);
#pragma unroll
        for (int i = 0; i < 4; i++)
            cp16(base + 18432 + soff + i * 16, pb + i * 4);
        asm volatile("cp.async.commit_group;" ::: "memory");
    }

    float acc[4][4][4];
#pragma unroll
    for (int mi = 0; mi < 4; mi++)
#pragma unroll
        for (int ni = 0; ni < 4; ni++)
#pragma unroll
            for (int r = 0; r < 4; r++) acc[mi][ni][r] = 0.f;

    // ---- mainloop
    for (int kt = 0; kt < KT; kt++) {
        asm volatile("cp.async.wait_group 2;" ::: "memory");
        __syncthreads();

        const int stg = kt % 3;
        const uint32_t sA = sb + stg * STG_B;
        const uint32_t sB = sA + 18432;

#pragma unroll
        for (int ks = 0; ks < 4; ks++) {
            uint32_t a[4][4], b[4][2];
#pragma unroll
            for (int mi = 0; mi < 4; mi++) {
                uint32_t ad = sA + (uint32_t)((warp_m * 64 + mi * 16 + gid) * 144
                                              + (ks * 8 + tig) * 4);
                a[mi][0] = f2tf32(ldsf(ad));
                a[mi][1] = f2tf32(ldsf(ad + 1152));   // +8 rows
                a[mi][2] = f2tf32(ldsf(ad + 16));     // +4 k
                a[mi][3] = f2tf32(ldsf(ad + 1168));
            }
#pragma unroll
            for (int ni = 0; ni < 4; ni++) {
                uint32_t bd = sB + (uint32_t)((warp_n * 32 + ni * 8 + gid) * 144
                                              + (ks * 8 + tig) * 4);
                b[ni][0] = f2tf32(ldsf(bd));
                b[ni][1] = f2tf32(ldsf(bd + 16));
            }
#pragma unroll
            for (int mi = 0; mi < 4; mi++)
#pragma unroll
                for (int ni = 0; ni < 4; ni++)
                    mma8(acc[mi][ni], a[mi], b[ni]);
        }

        __syncthreads();   // all warps done reading this stage
        const int kn = kt + 3;
        if (kn < KT) {
            uint32_t base = sb + stg * STG_B;
            const float* pa = gA + kn * 32;
            const float* pb = gB + kn * 32;
#pragma unroll
            for (int i = 0; i < 4; i++) cp16(base + soff + i * 16, pa + i * 4);
#pragma unroll
            for (int i = 0; i < 4; i++)
                cp16(base + 18432 + soff + i * 16, pb + i * 4);
        }
        asm volatile("cp.async.commit_group;" ::: "memory");
    }

    // ---- fused epilogue (accumulators in registers)
#pragma unroll
    for (int mi = 0; mi < 4; mi++) {
        const int gm = bm + warp_m * 64 + mi * 16 + gid;
#pragma unroll
        for (int ni = 0; ni < 4; ni++) {
            const int gn = bn + warp_n * 32 + ni * 8 + 2 * tig;
            const size_t i0 = (size_t)gm * N + gn;
            const size_t i1 = i0 + (size_t)8 * N;
            const float* c = acc[mi][ni];
            float2 o0, o1;
            if (EPI == 0) {
                float b0v = X[gn], b1v = X[gn + 1];
                o0.x = fast_tanh(c[0] + b0v);
                o0.y = fast_tanh(c[1] + b1v);
                o1.x = fast_tanh(c[2] + b0v);
                o1.y = fast_tanh(c[3] + b1v);
            } else if (EPI == 1) {
                float2 x0 = *reinterpret_cast<const float2*>(&X[i0]);
                float2 x1 = *reinterpret_cast<const float2*>(&X[i1]);
                o0.x = x0.x - fast_tanh(c[0]);
                o0.y = x0.y - fast_tanh(c[1]);
                o1.x = x1.x - fast_tanh(c[2]);
                o1.y = x1.y - fast_tanh(c[3]);
            } else {
                float2 x0 = *reinterpret_cast<const float2*>(&X[i0]);
                float2 x1 = *reinterpret_cast<const float2*>(&X[i1]);
                float2 d0 = *reinterpret_cast<const float2*>(&D[i0]);
                float2 d1 = *reinterpret_cast<const float2*>(&D[i1]);
                o0.x = d0.x + LRC * (c[0] - x0.x);
                o0.y = d0.y + LRC * (c[1] - x0.y);
                o1.x = d1.x + LRC * (c[2] - x1.x);
                o1.y = d1.y + LRC * (c[3] - x1.y);
            }
            *reinterpret_cast<float2*>(&D[i0]) = o0;
            *reinterpret_cast<float2*>(&D[i1]) = o1;
        }
    }
}

// ---------------------------------------------------------------------------
// Weight transpose: src (R x C) -> dst (C x R). R, C multiples of 32.
// ---------------------------------------------------------------------------
__global__ void transpose_k(const float* __restrict__ src,
                            float* __restrict__ dst, int R, int C)
{
    __shared__ float t[32][33];
    int bx = blockIdx.x * 32, by = blockIdx.y * 32;
    int x = bx + threadIdx.x;
#pragma unroll
    for (int i = 0; i < 32; i += 8)
        t[threadIdx.y + i][threadIdx.x] =
            src[(size_t)(by + threadIdx.y + i) * C + x];
    __syncthreads();
    int xo = by + threadIdx.x;
#pragma unroll
    for (int i = 0; i < 32; i += 8)
        dst[(size_t)(bx + threadIdx.y + i) * R + xo] =
            t[threadIdx.x][threadIdx.y + i];
}

// ---------------------------------------------------------------------------
// Output copy + deterministic two-stage sum-of-squares
// ---------------------------------------------------------------------------
__global__ void copy_k(const float* __restrict__ s, float* __restrict__ d,
                       int n4)
{
    int i = blockIdx.x * blockDim.x + threadIdx.x;
    if (i < n4)
        reinterpret_cast<float4*>(d)[i] =
            reinterpret_cast<const float4*>(s)[i];
}

__global__ void sumsq_partial(const float* __restrict__ x, long long n,
                              float* __restrict__ part)
{
    float s = 0.f;
    long long stride = (long long)gridDim.x * blockDim.x;
    for (long long i = (long long)blockIdx.x * blockDim.x + threadIdx.x;
         i < n; i += stride) {
        float v = x[i];
        s = fmaf(v, v, s);
    }
    __shared__ float sh[256];
    sh[threadIdx.x] = s;
    __syncthreads();
    for (int o = 128; o > 0; o >>= 1) {
        if (threadIdx.x < o) sh[threadIdx.x] += sh[threadIdx.x + o];
        __syncthreads();
    }
    if (threadIdx.x == 0) part[blockIdx.x] = sh[0];
}

__global__ void finalize_k(const float* __restrict__ part, int n,
                           float* __restrict__ out)
{
    float s = 0.f;
    for (int i = threadIdx.x; i < n; i += 256) s += part[i];
    __shared__ float sh[256];
    sh[threadIdx.x] = s;
    __syncthreads();
    for (int o = 128; o > 0; o >>= 1) {
        if (threadIdx.x < o) sh[threadIdx.x] += sh[threadIdx.x + o];
        __syncthreads();
    }
    if (threadIdx.x == 0) out[0] = 0.5f * sh[0];
}

// ---------------------------------------------------------------------------
// Launch
// ---------------------------------------------------------------------------
static inline dim3 ggrid(int N) { return dim3(N / 128, MB / 128); }

extern "C" void kernel_launch(void* const* d_in, const int* in_sizes, int n_in,
                              void* d_out, int out_size)
{
    const float* x  = (const float*)d_in[0];
    const float* W0 = (const float*)d_in[1];
    const float* b0 = (const float*)d_in[2];
    const float* W1 = (const float*)d_in[3];
    const float* b1 = (const float*)d_in[4];
    const float* W2 = (const float*)d_in[5];
    const float* b2 = (const float*)d_in[6];
    float* out = (float*)d_out;

    float *r1, *r2, *r3, *e0, *e1, *e2, *wt0, *wt1, *wt2, *part;
    cudaGetSymbolAddress((void**)&r1,  g_r1);
    cudaGetSymbolAddress((void**)&r2,  g_r2);
    cudaGetSymbolAddress((void**)&r3,  g_r3);
    cudaGetSymbolAddress((void**)&e0,  g_e0);
    cudaGetSymbolAddress((void**)&e1,  g_e1);
    cudaGetSymbolAddress((void**)&e2,  g_e2);
    cudaGetSymbolAddress((void**)&wt0, g_Wt0);
    cudaGetSymbolAddress((void**)&wt1, g_Wt1);
    cudaGetSymbolAddress((void**)&wt2, g_Wt2);
    cudaGetSymbolAddress((void**)&part, g_part);

    cudaFuncSetAttribute(tc_gemm<0>, cudaFuncAttributeMaxDynamicSharedMemorySize, SMEM_SZ);
    cudaFuncSetAttribute(tc_gemm<1>, cudaFuncAttributeMaxDynamicSharedMemorySize, SMEM_SZ);
    cudaFuncSetAttribute(tc_gemm<2>, cudaFuncAttributeMaxDynamicSharedMemorySize, SMEM_SZ);

    // ---- transpose weights once: Wt_i = W_i^T (K-major B for error GEMMs)
    transpose_k<<<dim3(D0 / 32, D1 / 32), dim3(32, 8)>>>(W0, wt0, D1, D0);
    transpose_k<<<dim3(D1 / 32, D2 / 32), dim3(32, 8)>>>(W1, wt1, D2, D1);
    transpose_k<<<dim3(D2 / 32, D3 / 32), dim3(32, 8)>>>(W2, wt2, D3, D2);

    // ---- feedforward init: r_{i+1} = tanh(r_i @ W_i^T + b_i)
    tc_gemm<0><<<ggrid(D1), 256, SMEM_SZ>>>(x,  W0, b0, r1, D1, D0);
    tc_gemm<0><<<ggrid(D2), 256, SMEM_SZ>>>(r1, W1, b1, r2, D2, D1);
    tc_gemm<0><<<ggrid(D3), 256, SMEM_SZ>>>(r2, W2, b2, r3, D3, D2);

    // ---- 20 PC inference steps
    for (int s = 0; s < NSTEPS; s++) {
        // errors: e_i = r_i - tanh(r_{i+1} @ W_i)   (B op = W_i^T, K-major)
        tc_gemm<1><<<ggrid(D2), 256, SMEM_SZ>>>(r3, wt2, r2, e2, D2, D3);
        tc_gemm<1><<<ggrid(D1), 256, SMEM_SZ>>>(r2, wt1, r1, e1, D1, D2);
        tc_gemm<1><<<ggrid(D0), 256, SMEM_SZ>>>(r1, wt0, x,  e0, D0, D1);
        // updates: r_i += LR * (e_{i-1} @ W_{i-1}^T - e_i)
        tc_gemm<2><<<ggrid(D1), 256, SMEM_SZ>>>(e0, W0, e1, r1, D1, D0);
        tc_gemm<2><<<ggrid(D2), 256, SMEM_SZ>>>(e1, W1, e2, r2, D2, D1);
        tc_gemm<2><<<ggrid(D3), 256, SMEM_SZ>>>(e2, W2, r3, r3, D3, D2);
    }

    // ---- final errors (for total_error)
    tc_gemm<1><<<ggrid(D2), 256, SMEM_SZ>>>(r3, wt2, r2, e2, D2, D3);
    tc_gemm<1><<<ggrid(D1), 256, SMEM_SZ>>>(r2, wt1, r1, e1, D1, D2);
    tc_gemm<1><<<ggrid(D0), 256, SMEM_SZ>>>(r1, wt0, x,  e0, D0, D1);

    // ---- output r3
    const int n_r3 = MB * D3;
    copy_k<<<(n_r3 / 4 + 255) / 256, 256>>>(r3, out, n_r3 / 4);

    // ---- total_error = 0.5 * (|e0|^2 + |e1|^2 + |e2|^2 + |r3|^2)
    sumsq_partial<<<1024, 256>>>(e0, (long long)MB * D0, part + 0);
    sumsq_partial<<<1024, 256>>>(e1, (long long)MB * D1, part + 1024);
    sumsq_partial<<<1024, 256>>>(e2, (long long)MB * D2, part + 2048);
    sumsq_partial<<<1024, 256>>>(r3, (long long)MB * D3, part + 3072);
    finalize_k<<<1, 256>>>(part, 4096, out + (out_size - 1));
}

// round 7
// speedup vs baseline: 1.1519x; 1.1519x over previous
#include <cuda_runtime.h>
#include <cstdint>
#include <math.h>

// ---------------------------------------------------------------------------
// PcLinearBlock: ARCH=(1024,2048,2048,512), BATCH=4096, STEPS=20, LR=0.1
// tf32 mma.sync m16n8k8, 128x128x32 tile, cp.async 3-stage pipeline.
// GEMM operands pre-rounded to tf32 and stored in k-permuted (0,4,1,5,2,6,3,7)
// layout -> no in-loop cvt, 64-bit conflict-free fragment loads.
// ---------------------------------------------------------------------------

#define MB 4096
#define D0 1024
#define D1 2048
#define D2 2048
#define D3 512
#define NSTEPS 20
#define LRC 0.1f

// ---- exact fp32 state (epilogue math / reductions / output) ----
__device__ __align__(128) float g_r1[(size_t)MB * D1];
__device__ __align__(128) float g_r2[(size_t)MB * D2];
__device__ __align__(128) float g_r3[(size_t)MB * D3];
__device__ __align__(128) float g_e0[(size_t)MB * D0];
__device__ __align__(128) float g_e1[(size_t)MB * D1];
__device__ __align__(128) float g_e2[(size_t)MB * D2];
// ---- tf32-rounded, k-permuted GEMM operand shadows ----
__device__ __align__(128) float g_xr [(size_t)MB * D0];
__device__ __align__(128) float g_r1r[(size_t)MB * D1];
__device__ __align__(128) float g_r2r[(size_t)MB * D2];
__device__ __align__(128) float g_r3r[(size_t)MB * D3];
__device__ __align__(128) float g_e0r[(size_t)MB * D0];
__device__ __align__(128) float g_e1r[(size_t)MB * D1];
__device__ __align__(128) float g_e2r[(size_t)MB * D2];
__device__ __align__(128) float g_W0r[(size_t)D1 * D0];
__device__ __align__(128) float g_W1r[(size_t)D2 * D1];
__device__ __align__(128) float g_W2r[(size_t)D3 * D2];
__device__ __align__(128) float g_Wt0[(size_t)D0 * D1];
__device__ __align__(128) float g_Wt1[(size_t)D1 * D2];
__device__ __align__(128) float g_Wt2[(size_t)D2 * D3];
__device__ float g_part[4096];

// ---------------------------------------------------------------------------
// helpers
// ---------------------------------------------------------------------------
__device__ __forceinline__ uint32_t s2u(const void* p) {
    uint32_t a;
    asm("{ .reg .u64 t; cvta.to.shared.u64 t, %1; cvt.u32.u64 %0, t; }"
        : "=r"(a) : "l"(p));
    return a;
}
__device__ __forceinline__ void cp16(uint32_t dst, const void* src) {
    asm volatile("cp.async.cg.shared.global [%0], [%1], 16;"
                 :: "r"(dst), "l"(src));
}
__device__ __forceinline__ void lds2(uint32_t& x, uint32_t& y, uint32_t a) {
    asm volatile("ld.shared.v2.b32 {%0,%1}, [%2];"
                 : "=r"(x), "=r"(y) : "r"(a));
}
__device__ __forceinline__ float rnd_tf32(float f) {
    uint32_t u;
    asm("cvt.rna.tf32.f32 %0, %1;" : "=r"(u) : "f"(f));
    return __uint_as_float(u);
}
__device__ __forceinline__ void mma8(float* c, const uint32_t* a,
                                     const uint32_t* b) {
    asm volatile(
        "mma.sync.aligned.m16n8k8.row.col.f32.tf32.tf32.f32 "
        "{%0,%1,%2,%3}, {%4,%5,%6,%7}, {%8,%9}, {%0,%1,%2,%3};"
        : "+f"(c[0]), "+f"(c[1]), "+f"(c[2]), "+f"(c[3])
        : "r"(a[0]), "r"(a[1]), "r"(a[2]), "r"(a[3]), "r"(b[0]), "r"(b[1]));
}
__device__ __forceinline__ float fast_tanh(float x) {
    float e = __expf(2.0f * x);
    return 1.0f - 2.0f / (e + 1.0f);
}
// permute k within 8-group to (0,4,1,5,2,6,3,7): p(j) = ((j&3)<<1)|(j>>2)
__device__ __forceinline__ int perm8(int j) {
    return ((j & 3) << 1) | ((j >> 2) & 1);
}

// ---------------------------------------------------------------------------
// tf32 GEMM:  C[m,n] = sum_k A[m,k]*B[n,k]
//   A (MxK), B (NxK): tf32-rounded, k-permuted. 128x128x32 tile, 256 thr.
// Smem stage: A 128x128B + B 128x128B = 32KB; XOR-swizzle w^=8*(row&3).
// EPI 0: D = tanh(acc + X[n]);  EPI 1: D = X - tanh(acc);
// EPI 2: D += LR*(acc - X).   Writes exact D and rounded+permuted Dr.
// ---------------------------------------------------------------------------
#define STG_B   32768
#define SMEM_SZ (3 * STG_B)

template <int EPI>
__global__ void __launch_bounds__(256, 2)
tc_gemm(const float* __restrict__ A, const float* __restrict__ B,
        const float* __restrict__ X, float* __restrict__ D,
        float* __restrict__ Dr, int N, int K)
{
    extern __shared__ char smem[];
    const uint32_t sb = s2u(smem);
    const int tid = threadIdx.x;
    const int wid = tid >> 5, lane = tid & 31;
    const int gid = lane >> 2, tig = lane & 3;
    const int warp_m = wid & 1;
    const int warp_n = wid >> 1;
    const int bm = blockIdx.y * 128, bn = blockIdx.x * 128;

    // global->smem: thread t copies 64B of row t/2 (16B chunks, swizzled)
    const int ar = tid >> 1;
    const int half = tid & 1;
    const float* gA = A + (size_t)(bm + ar) * K + half * 16;
    const float* gB = B + (size_t)(bn + ar) * K + half * 16;
    uint32_t sw[4];
#pragma unroll
    for (int i = 0; i < 4; i++) {
        int cc = half * 4 + i;
        sw[i] = (uint32_t)(ar * 128 + ((cc ^ (2 * (ar & 3))) * 16));
    }

    const int KT = K >> 5;

    // ---- prologue
#pragma unroll
    for (int kt = 0; kt < 3; kt++) {
        uint32_t base = sb + kt * STG_B;
        const float* pa = gA + kt * 32;
        const float* pb = gB + kt * 32;
#pragma unroll
        for (int i = 0; i < 4; i++) cp16(base + sw[i], pa + i * 4);
#pragma unroll
        for (int i = 0; i < 4; i++) cp16(base + 16384 + sw[i], pb + i * 4);
        asm volatile("cp.async.commit_group;" ::: "memory");
    }

    float acc[4][4][4];
#pragma unroll
    for (int mi = 0; mi < 4; mi++)
#pragma unroll
        for (int ni = 0; ni < 4; ni++)
#pragma unroll
            for (int r = 0; r < 4; r++) acc[mi][ni][r] = 0.f;

    const int g3 = gid & 3;

    // ---- mainloop
    for (int kt = 0; kt < KT; kt++) {
        asm volatile("cp.async.wait_group 2;" ::: "memory");
        __syncthreads();

        const int stg = kt % 3;
        const uint32_t sA = sb + stg * STG_B;
        const uint32_t sB = sA + 16384;

#pragma unroll
        for (int ks = 0; ks < 4; ks++) {
            const uint32_t coloff = (uint32_t)(32 * (ks ^ g3) + 8 * tig);
            uint32_t a[4][4], b[4][2];
#pragma unroll
            for (int mi = 0; mi < 4; mi++) {
                uint32_t ad = sA +
                    (uint32_t)((warp_m * 64 + mi * 16 + gid) * 128) + coloff;
                lds2(a[mi][0], a[mi][2], ad);
                lds2(a[mi][1], a[mi][3], ad + 1024);   // +8 rows
            }
#pragma unroll
            for (int ni = 0; ni < 4; ni++) {
                uint32_t bd = sB +
                    (uint32_t)((warp_n * 32 + ni * 8 + gid) * 128) + coloff;
                lds2(b[ni][0], b[ni][1], bd);
            }
#pragma unroll
            for (int mi = 0; mi < 4; mi++)
#pragma unroll
                for (int ni = 0; ni < 4; ni++)
                    mma8(acc[mi][ni], a[mi], b[ni]);
        }

        __syncthreads();
        const int kn = kt + 3;
        if (kn < KT) {
            uint32_t base = sb + stg * STG_B;
            const float* pa = gA + kn * 32;
            const float* pb = gB + kn * 32;
#pragma unroll
            for (int i = 0; i < 4; i++) cp16(base + sw[i], pa + i * 4);
#pragma unroll
            for (int i = 0; i < 4; i++) cp16(base + 16384 + sw[i], pb + i * 4);
        }
        asm volatile("cp.async.commit_group;" ::: "memory");
    }

    // ---- fused epilogue: exact store + rounded/permuted shadow store
#pragma unroll
    for (int mi = 0; mi < 4; mi++) {
        const int gm = bm + warp_m * 64 + mi * 16 + gid;
#pragma unroll
        for (int ni = 0; ni < 4; ni++) {
            const int gn = bn + warp_n * 32 + ni * 8 + 2 * tig;
            const size_t i0 = (size_t)gm * N + gn;
            const size_t i1 = i0 + (size_t)8 * N;
            const float* c = acc[mi][ni];
            float2 o0, o1;
            if (EPI == 0) {
                float b0v = X[gn], b1v = X[gn + 1];
                o0.x = fast_tanh(c[0] + b0v);
                o0.y = fast_tanh(c[1] + b1v);
                o1.x = fast_tanh(c[2] + b0v);
                o1.y = fast_tanh(c[3] + b1v);
            } else if (EPI == 1) {
                float2 x0 = *reinterpret_cast<const float2*>(&X[i0]);
                float2 x1 = *reinterpret_cast<const float2*>(&X[i1]);
                o0.x = x0.x - fast_tanh(c[0]);
                o0.y = x0.y - fast_tanh(c[1]);
                o1.x = x1.x - fast_tanh(c[2]);
                o1.y = x1.y - fast_tanh(c[3]);
            } else {
                float2 x0 = *reinterpret_cast<const float2*>(&X[i0]);
                float2 x1 = *reinterpret_cast<const float2*>(&X[i1]);
                float2 d0 = *reinterpret_cast<const float2*>(&D[i0]);
                float2 d1 = *reinterpret_cast<const float2*>(&D[i1]);
                o0.x = d0.x + LRC * (c[0] - x0.x);
                o0.y = d0.y + LRC * (c[1] - x0.y);
                o1.x = d1.x + LRC * (c[2] - x1.x);
                o1.y = d1.y + LRC * (c[3] - x1.y);
            }
            *reinterpret_cast<float2*>(&D[i0]) = o0;
            *reinterpret_cast<float2*>(&D[i1]) = o1;
            // rounded + k-permuted shadow
            const int nb = gn & ~7;
            const int p0 = nb + perm8(gn & 7);
            const int p1 = nb + perm8((gn + 1) & 7);
            const size_t rowr0 = (size_t)gm * N;
            const size_t rowr1 = rowr0 + (size_t)8 * N;
            Dr[rowr0 + p0] = rnd_tf32(o0.x);
            Dr[rowr0 + p1] = rnd_tf32(o0.y);
            Dr[rowr1 + p0] = rnd_tf32(o1.x);
            Dr[rowr1 + p1] = rnd_tf32(o1.y);
        }
    }
}

// ---------------------------------------------------------------------------
// prep: round to tf32 + permute columns within 8-groups
// ---------------------------------------------------------------------------
__global__ void roundperm_k(const float* __restrict__ src,
                            float* __restrict__ dst, long long n)
{
    long long i = (long long)blockIdx.x * blockDim.x + threadIdx.x;
    if (i < n) {
        long long base = i & ~7LL;
        int j = (int)(i & 7);
        dst[base + perm8(j)] = rnd_tf32(src[i]);
    }
}

// transpose + round + permute: src (R x C) -> dst (C x R), dst cols permuted
__global__ void transpose_rp_k(const float* __restrict__ src,
                               float* __restrict__ dst, int R, int C)
{
    __shared__ float t[32][33];
    int bx = blockIdx.x * 32, by = blockIdx.y * 32;
    int x = bx + threadIdx.x;
#pragma unroll
    for (int i = 0; i < 32; i += 8)
        t[threadIdx.y + i][threadIdx.x] =
            src[(size_t)(by + threadIdx.y + i) * C + x];
    __syncthreads();
    int xo = by + threadIdx.x;
    int xp = (xo & ~7) | perm8(xo & 7);
#pragma unroll
    for (int i = 0; i < 32; i += 8)
        dst[(size_t)(bx + threadIdx.y + i) * R + xp] =
            rnd_tf32(t[threadIdx.x][threadIdx.y + i]);
}

// ---------------------------------------------------------------------------
// output copy + deterministic two-stage sum-of-squares
// ---------------------------------------------------------------------------
__global__ void copy_k(const float* __restrict__ s, float* __restrict__ d,
                       int n4)
{
    int i = blockIdx.x * blockDim.x + threadIdx.x;
    if (i < n4)
        reinterpret_cast<float4*>(d)[i] =
            reinterpret_cast<const float4*>(s)[i];
}

__global__ void sumsq_partial(const float* __restrict__ x, long long n,
                              float* __restrict__ part)
{
    float s = 0.f;
    long long stride = (long long)gridDim.x * blockDim.x;
    for (long long i = (long long)blockIdx.x * blockDim.x + threadIdx.x;
         i < n; i += stride) {
        float v = x[i];
        s = fmaf(v, v, s);
    }
    __shared__ float sh[256];
    sh[threadIdx.x] = s;
    __syncthreads();
    for (int o = 128; o > 0; o >>= 1) {
        if (threadIdx.x < o) sh[threadIdx.x] += sh[threadIdx.x + o];
        __syncthreads();
    }
    if (threadIdx.x == 0) part[blockIdx.x] = sh[0];
}

__global__ void finalize_k(const float* __restrict__ part, int n,
                           float* __restrict__ out)
{
    float s = 0.f;
    for (int i = threadIdx.x; i < n; i += 256) s += part[i];
    __shared__ float sh[256];
    sh[threadIdx.x] = s;
    __syncthreads();
    for (int o = 128; o > 0; o >>= 1) {
        if (threadIdx.x < o) sh[threadIdx.x] += sh[threadIdx.x + o];
        __syncthreads();
    }
    if (threadIdx.x == 0) out[0] = 0.5f * sh[0];
}

// ---------------------------------------------------------------------------
// Launch
// ---------------------------------------------------------------------------
static inline dim3 ggrid(int N) { return dim3(N / 128, MB / 128); }

extern "C" void kernel_launch(void* const* d_in, const int* in_sizes, int n_in,
                              void* d_out, int out_size)
{
    const float* x  = (const float*)d_in[0];
    const float* W0 = (const float*)d_in[1];
    const float* b0 = (const float*)d_in[2];
    const float* W1 = (const float*)d_in[3];
    const float* b1 = (const float*)d_in[4];
    const float* W2 = (const float*)d_in[5];
    const float* b2 = (const float*)d_in[6];
    float* out = (float*)d_out;

    float *r1, *r2, *r3, *e0, *e1, *e2;
    float *xr, *r1r, *r2r, *r3r, *e0r, *e1r, *e2r;
    float *w0r, *w1r, *w2r, *wt0, *wt1, *wt2, *part;
    cudaGetSymbolAddress((void**)&r1,  g_r1);
    cudaGetSymbolAddress((void**)&r2,  g_r2);
    cudaGetSymbolAddress((void**)&r3,  g_r3);
    cudaGetSymbolAddress((void**)&e0,  g_e0);
    cudaGetSymbolAddress((void**)&e1,  g_e1);
    cudaGetSymbolAddress((void**)&e2,  g_e2);
    cudaGetSymbolAddress((void**)&xr,  g_xr);
    cudaGetSymbolAddress((void**)&r1r, g_r1r);
    cudaGetSymbolAddress((void**)&r2r, g_r2r);
    cudaGetSymbolAddress((void**)&r3r, g_r3r);
    cudaGetSymbolAddress((void**)&e0r, g_e0r);
    cudaGetSymbolAddress((void**)&e1r, g_e1r);
    cudaGetSymbolAddress((void**)&e2r, g_e2r);
    cudaGetSymbolAddress((void**)&w0r, g_W0r);
    cudaGetSymbolAddress((void**)&w1r, g_W1r);
    cudaGetSymbolAddress((void**)&w2r, g_W2r);
    cudaGetSymbolAddress((void**)&wt0, g_Wt0);
    cudaGetSymbolAddress((void**)&wt1, g_Wt1);
    cudaGetSymbolAddress((void**)&wt2, g_Wt2);
    cudaGetSymbolAddress((void**)&part, g_part);

    cudaFuncSetAttribute(tc_gemm<0>, cudaFuncAttributeMaxDynamicSharedMemorySize, SMEM_SZ);
    cudaFuncSetAttribute(tc_gemm<1>, cudaFuncAttributeMaxDynamicSharedMemorySize, SMEM_SZ);
    cudaFuncSetAttribute(tc_gemm<2>, cudaFuncAttributeMaxDynamicSharedMemorySize, SMEM_SZ);

    // ---- prep: rounded (+permuted) operand copies
    roundperm_k<<<(int)(((long long)MB * D0 + 255) / 256), 256>>>(x, xr, (long long)MB * D0);
    roundperm_k<<<(int)(((long long)D1 * D0 + 255) / 256), 256>>>(W0, w0r, (long long)D1 * D0);
    roundperm_k<<<(int)(((long long)D2 * D1 + 255) / 256), 256>>>(W1, w1r, (long long)D2 * D1);
    roundperm_k<<<(int)(((long long)D3 * D2 + 255) / 256), 256>>>(W2, w2r, (long long)D3 * D2);
    transpose_rp_k<<<dim3(D0 / 32, D1 / 32), dim3(32, 8)>>>(W0, wt0, D1, D0);
    transpose_rp_k<<<dim3(D1 / 32, D2 / 32), dim3(32, 8)>>>(W1, wt1, D2, D1);
    transpose_rp_k<<<dim3(D2 / 32, D3 / 32), dim3(32, 8)>>>(W2, wt2, D3, D2);

    // ---- feedforward init: r_{i+1} = tanh(r_i @ W_i^T + b_i)
    tc_gemm<0><<<ggrid(D1), 256, SMEM_SZ>>>(xr,  w0r, b0, r1, r1r, D1, D0);
    tc_gemm<0><<<ggrid(D2), 256, SMEM_SZ>>>(r1r, w1r, b1, r2, r2r, D2, D1);
    tc_gemm<0><<<ggrid(D3), 256, SMEM_SZ>>>(r2r, w2r, b2, r3, r3r, D3, D2);

    // ---- 20 PC inference steps
    for (int s = 0; s < NSTEPS; s++) {
        // errors: e_i = r_i - tanh(r_{i+1} @ W_i)
        tc_gemm<1><<<ggrid(D2), 256, SMEM_SZ>>>(r3r, wt2, r2, e2, e2r, D2, D3);
        tc_gemm<1><<<ggrid(D1), 256, SMEM_SZ>>>(r2r, wt1, r1, e1, e1r, D1, D2);
        tc_gemm<1><<<ggrid(D0), 256, SMEM_SZ>>>(r1r, wt0, x,  e0, e0r, D0, D1);
        // updates: r_i += LR * (e_{i-1} @ W_{i-1}^T - e_i)
        tc_gemm<2><<<ggrid(D1), 256, SMEM_SZ>>>(e0r, w0r, e1, r1, r1r, D1, D0);
        tc_gemm<2><<<ggrid(D2), 256, SMEM_SZ>>>(e1r, w1r, e2, r2, r2r, D2, D1);
        tc_gemm<2><<<ggrid(D3), 256, SMEM_SZ>>>(e2r, w2r, r3, r3, r3r, D3, D2);
    }

    // ---- final errors
    tc_gemm<1><<<ggrid(D2), 256, SMEM_SZ>>>(r3r, wt2, r2, e2, e2r, D2, D3);
    tc_gemm<1><<<ggrid(D1), 256, SMEM_SZ>>>(r2r, wt1, r1, e1, e1r, D1, D2);
    tc_gemm<1><<<ggrid(D0), 256, SMEM_SZ>>>(r1r, wt0, x,  e0, e0r, D0, D1);

    // ---- output r3
    const int n_r3 = MB * D3;
    copy_k<<<(n_r3 / 4 + 255) / 256, 256>>>(r3, out, n_r3 / 4);

    // ---- total_error = 0.5 * (|e0|^2 + |e1|^2 + |e2|^2 + |r3|^2)
    sumsq_partial<<<1024, 256>>>(e0, (long long)MB * D0, part + 0);
    sumsq_partial<<<1024, 256>>>(e1, (long long)MB * D1, part + 1024);
    sumsq_partial<<<1024, 256>>>(e2, (long long)MB * D2, part + 2048);
    sumsq_partial<<<1024, 256>>>(r3, (long long)MB * D3, part + 3072);
    finalize_k<<<1, 256>>>(part, 4096, out + (out_size - 1));
}

// round 8
// speedup vs baseline: 1.1528x; 1.0007x over previous
#include <cuda_runtime.h>
#include <cstdint>
#include <math.h>

// ---------------------------------------------------------------------------
// PcLinearBlock: ARCH=(1024,2048,2048,512), BATCH=4096, STEPS=20, LR=0.1
// tf32 mma.sync m16n8k8, 128x128x32 tile, cp.async 3-stage pipeline.
// GEMM operands pre-rounded to tf32 and stored in k-permuted (0,4,1,5,2,6,3,7)
// layout -> no in-loop cvt, 64-bit conflict-free fragment loads.
// ---------------------------------------------------------------------------

#define MB 4096
#define D0 1024
#define D1 2048
#define D2 2048
#define D3 512
#define NSTEPS 20
#define LRC 0.1f

// ---- exact fp32 state (epilogue math / reductions / output) ----
__device__ __align__(128) float g_r1[(size_t)MB * D1];
__device__ __align__(128) float g_r2[(size_t)MB * D2];
__device__ __align__(128) float g_r3[(size_t)MB * D3];
__device__ __align__(128) float g_e0[(size_t)MB * D0];
__device__ __align__(128) float g_e1[(size_t)MB * D1];
__device__ __align__(128) float g_e2[(size_t)MB * D2];
// ---- tf32-rounded, k-permuted GEMM operand shadows ----
__device__ __align__(128) float g_xr [(size_t)MB * D0];
__device__ __align__(128) float g_r1r[(size_t)MB * D1];
__device__ __align__(128) float g_r2r[(size_t)MB * D2];
__device__ __align__(128) float g_r3r[(size_t)MB * D3];
__device__ __align__(128) float g_e0r[(size_t)MB * D0];
__device__ __align__(128) float g_e1r[(size_t)MB * D1];
__device__ __align__(128) float g_e2r[(size_t)MB * D2];
__device__ __align__(128) float g_W0r[(size_t)D1 * D0];
__device__ __align__(128) float g_W1r[(size_t)D2 * D1];
__device__ __align__(128) float g_W2r[(size_t)D3 * D2];
__device__ __align__(128) float g_Wt0[(size_t)D0 * D1];
__device__ __align__(128) float g_Wt1[(size_t)D1 * D2];
__device__ __align__(128) float g_Wt2[(size_t)D2 * D3];
__device__ float g_part[4096];

// ---------------------------------------------------------------------------
// helpers
// ---------------------------------------------------------------------------
__device__ __forceinline__ uint32_t s2u(const void* p) {
    uint32_t a;
    asm("{ .reg .u64 t; cvta.to.shared.u64 t, %1; cvt.u32.u64 %0, t; }"
        : "=r"(a) : "l"(p));
    return a;
}
__device__ __forceinline__ void cp16(uint32_t dst, const void* src) {
    asm volatile("cp.async.cg.shared.global [%0], [%1], 16;"
                 :: "r"(dst), "l"(src));
}
__device__ __forceinline__ void lds2(uint32_t& x, uint32_t& y, uint32_t a) {
    asm volatile("ld.shared.v2.b32 {%0,%1}, [%2];"
                 : "=r"(x), "=r"(y) : "r"(a));
}
__device__ __forceinline__ float rnd_tf32(float f) {
    uint32_t u;
    asm("cvt.rna.tf32.f32 %0, %1;" : "=r"(u) : "f"(f));
    return __uint_as_float(u);
}
__device__ __forceinline__ void mma8(float* c, const uint32_t* a,
                                     const uint32_t* b) {
    asm volatile(
        "mma.sync.aligned.m16n8k8.row.col.f32.tf32.tf32.f32 "
        "{%0,%1,%2,%3}, {%4,%5,%6,%7}, {%8,%9}, {%0,%1,%2,%3};"
        : "+f"(c[0]), "+f"(c[1]), "+f"(c[2]), "+f"(c[3])
        : "r"(a[0]), "r"(a[1]), "r"(a[2]), "r"(a[3]), "r"(b[0]), "r"(b[1]));
}
__device__ __forceinline__ float fast_tanh(float x) {
    float e = __expf(2.0f * x);
    return 1.0f - 2.0f / (e + 1.0f);
}
// permute k within 8-group to (0,4,1,5,2,6,3,7): p(j) = ((j&3)<<1)|(j>>2)
__device__ __forceinline__ int perm8(int j) {
    return ((j & 3) << 1) | ((j >> 2) & 1);
}

// ---------------------------------------------------------------------------
// tf32 GEMM:  C[m,n] = sum_k A[m,k]*B[n,k]
//   A (MxK), B (NxK): tf32-rounded, k-permuted. 128x128x32 tile, 256 thr.
// Smem stage: A 128x128B + B 128x128B = 32KB; XOR-swizzle w^=8*(row&3).
// EPI 0: D = tanh(acc + X[n]);  EPI 1: D = X - tanh(acc);
// EPI 2: D += LR*(acc - X).   Writes exact D and rounded+permuted Dr.
// ---------------------------------------------------------------------------
#define STG_B   32768
#define SMEM_SZ (3 * STG_B)

template <int EPI>
__global__ void __launch_bounds__(256, 2)
tc_gemm(const float* __restrict__ A, const float* __restrict__ B,
        const float* __restrict__ X, float* __restrict__ D,
        float* __restrict__ Dr, int N, int K)
{
    extern __shared__ char smem[];
    const uint32_t sb = s2u(smem);
    const int tid = threadIdx.x;
    const int wid = tid >> 5, lane = tid & 31;
    const int gid = lane >> 2, tig = lane & 3;
    const int warp_m = wid & 1;
    const int warp_n = wid >> 1;
    const int bm = blockIdx.y * 128, bn = blockIdx.x * 128;

    // global->smem: thread t copies 64B of row t/2 (16B chunks, swizzled)
    const int ar = tid >> 1;
    const int half = tid & 1;
    const float* gA = A + (size_t)(bm + ar) * K + half * 16;
    const float* gB = B + (size_t)(bn + ar) * K + half * 16;
    uint32_t sw[4];
#pragma unroll
    for (int i = 0; i < 4; i++) {
        int cc = half * 4 + i;
        sw[i] = (uint32_t)(ar * 128 + ((cc ^ (2 * (ar & 3))) * 16));
    }

    const int KT = K >> 5;

    // ---- prologue
#pragma unroll
    for (int kt = 0; kt < 3; kt++) {
        uint32_t base = sb + kt * STG_B;
        const float* pa = gA + kt * 32;
        const float* pb = gB + kt * 32;
#pragma unroll
        for (int i = 0; i < 4; i++) cp16(base + sw[i], pa + i * 4);
#pragma unroll
        for (int i = 0; i < 4; i++) cp16(base + 16384 + sw[i], pb + i * 4);
        asm volatile("cp.async.commit_group;" ::: "memory");
    }

    float acc[4][4][4];
#pragma unroll
    for (int mi = 0; mi < 4; mi++)
#pragma unroll
        for (int ni = 0; ni < 4; ni++)
#pragma unroll
            for (int r = 0; r < 4; r++) acc[mi][ni][r] = 0.f;

    const int g3 = gid & 3;

    // ---- mainloop
    for (int kt = 0; kt < KT; kt++) {
        asm volatile("cp.async.wait_group 2;" ::: "memory");
        __syncthreads();

        const int stg = kt % 3;
        const uint32_t sA = sb + stg * STG_B;
        const uint32_t sB = sA + 16384;

#pragma unroll
        for (int ks = 0; ks < 4; ks++) {
            const uint32_t coloff = (uint32_t)(32 * (ks ^ g3) + 8 * tig);
            uint32_t a[4][4], b[4][2];
#pragma unroll
            for (int mi = 0; mi < 4; mi++) {
                uint32_t ad = sA +
                    (uint32_t)((warp_m * 64 + mi * 16 + gid) * 128) + coloff;
                lds2(a[mi][0], a[mi][2], ad);
                lds2(a[mi][1], a[mi][3], ad + 1024);   // +8 rows
            }
#pragma unroll
            for (int ni = 0; ni < 4; ni++) {
                uint32_t bd = sB +
                    (uint32_t)((warp_n * 32 + ni * 8 + gid) * 128) + coloff;
                lds2(b[ni][0], b[ni][1], bd);
            }
#pragma unroll
            for (int mi = 0; mi < 4; mi++)
#pragma unroll
                for (int ni = 0; ni < 4; ni++)
                    mma8(acc[mi][ni], a[mi], b[ni]);
        }

        __syncthreads();
        const int kn = kt + 3;
        if (kn < KT) {
            uint32_t base = sb + stg * STG_B;
            const float* pa = gA + kn * 32;
            const float* pb = gB + kn * 32;
#pragma unroll
            for (int i = 0; i < 4; i++) cp16(base + sw[i], pa + i * 4);
#pragma unroll
            for (int i = 0; i < 4; i++) cp16(base + 16384 + sw[i], pb + i * 4);
        }
        asm volatile("cp.async.commit_group;" ::: "memory");
    }

    // ---- fused epilogue: exact store + rounded/permuted shadow store
#pragma unroll
    for (int mi = 0; mi < 4; mi++) {
        const int gm = bm + warp_m * 64 + mi * 16 + gid;
#pragma unroll
        for (int ni = 0; ni < 4; ni++) {
            const int gn = bn + warp_n * 32 + ni * 8 + 2 * tig;
            const size_t i0 = (size_t)gm * N + gn;
            const size_t i1 = i0 + (size_t)8 * N;
            const float* c = acc[mi][ni];
            float2 o0, o1;
            if (EPI == 0) {
                float b0v = X[gn], b1v = X[gn + 1];
                o0.x = fast_tanh(c[0] + b0v);
                o0.y = fast_tanh(c[1] + b1v);
                o1.x = fast_tanh(c[2] + b0v);
                o1.y = fast_tanh(c[3] + b1v);
            } else if (EPI == 1) {
                float2 x0 = *reinterpret_cast<const float2*>(&X[i0]);
                float2 x1 = *reinterpret_cast<const float2*>(&X[i1]);
                o0.x = x0.x - fast_tanh(c[0]);
                o0.y = x0.y - fast_tanh(c[1]);
                o1.x = x1.x - fast_tanh(c[2]);
                o1.y = x1.y - fast_tanh(c[3]);
            } else {
                float2 x0 = *reinterpret_cast<const float2*>(&X[i0]);
                float2 x1 = *reinterpret_cast<const float2*>(&X[i1]);
                float2 d0 = *reinterpret_cast<const float2*>(&D[i0]);
                float2 d1 = *reinterpret_cast<const float2*>(&D[i1]);
                o0.x = d0.x + LRC * (c[0] - x0.x);
                o0.y = d0.y + LRC * (c[1] - x0.y);
                o1.x = d1.x + LRC * (c[2] - x1.x);
                o1.y = d1.y + LRC * (c[3] - x1.y);
            }
            *reinterpret_cast<float2*>(&D[i0]) = o0;
            *reinterpret_cast<float2*>(&D[i1]) = o1;
            // rounded + k-permuted shadow
            const int nb = gn & ~7;
            const int p0 = nb + perm8(gn & 7);
            const int p1 = nb + perm8((gn + 1) & 7);
            const size_t rowr0 = (size_t)gm * N;
            const size_t rowr1 = rowr0 + (size_t)8 * N;
            Dr[rowr0 + p0] = rnd_tf32(o0.x);
            Dr[rowr0 + p1] = rnd_tf32(o0.y);
            Dr[rowr1 + p0] = rnd_tf32(o1.x);
            Dr[rowr1 + p1] = rnd_tf32(o1.y);
        }
    }
}

// ---------------------------------------------------------------------------
// prep: round to tf32 + permute columns within 8-groups
// ---------------------------------------------------------------------------
__global__ void roundperm_k(const float* __restrict__ src,
                            float* __restrict__ dst, long long n)
{
    long long i = (long long)blockIdx.x * blockDim.x + threadIdx.x;
    if (i < n) {
        long long base = i & ~7LL;
        int j = (int)(i & 7);
        dst[base + perm8(j)] = rnd_tf32(src[i]);
    }
}

// transpose + round + permute: src (R x C) -> dst (C x R), dst cols permuted
__global__ void transpose_rp_k(const float* __restrict__ src,
                               float* __restrict__ dst, int R, int C)
{
    __shared__ float t[32][33];
    int bx = blockIdx.x * 32, by = blockIdx.y * 32;
    int x = bx + threadIdx.x;
#pragma unroll
    for (int i = 0; i < 32; i += 8)
        t[threadIdx.y + i][threadIdx.x] =
            src[(size_t)(by + threadIdx.y + i) * C + x];
    __syncthreads();
    int xo = by + threadIdx.x;
    int xp = (xo & ~7) | perm8(xo & 7);
#pragma unroll
    for (int i = 0; i < 32; i += 8)
        dst[(size_t)(bx + threadIdx.y + i) * R + xp] =
            rnd_tf32(t[threadIdx.x][threadIdx.y + i]);
}

// ---------------------------------------------------------------------------
// output copy + deterministic two-stage sum-of-squares
// ---------------------------------------------------------------------------
__global__ void copy_k(const float* __restrict__ s, float* __restrict__ d,
                       int n4)
{
    int i = blockIdx.x * blockDim.x + threadIdx.x;
    if (i < n4)
        reinterpret_cast<float4*>(d)[i] =
            reinterpret_cast<const float4*>(s)[i];
}

__global__ void sumsq_partial(const float* __restrict__ x, long long n,
                              float* __restrict__ part)
{
    float s = 0.f;
    long long stride = (long long)gridDim.x * blockDim.x;
    for (long long i = (long long)blockIdx.x * blockDim.x + threadIdx.x;
         i < n; i += stride) {
        float v = x[i];
        s = fmaf(v, v, s);
    }
    __shared__ float sh[256];
    sh[threadIdx.x] = s;
    __syncthreads();
    for (int o = 128; o > 0; o >>= 1) {
        if (threadIdx.x < o) sh[threadIdx.x] += sh[threadIdx.x + o];
        __syncthreads();
    }
    if (threadIdx.x == 0) part[blockIdx.x] = sh[0];
}

__global__ void finalize_k(const float* __restrict__ part, int n,
                           float* __restrict__ out)
{
    float s = 0.f;
    for (int i = threadIdx.x; i < n; i += 256) s += part[i];
    __shared__ float sh[256];
    sh[threadIdx.x] = s;
    __syncthreads();
    for (int o = 128; o > 0; o >>= 1) {
        if (threadIdx.x < o) sh[threadIdx.x] += sh[threadIdx.x + o];
        __syncthreads();
    }
    if (threadIdx.x == 0) out[0] = 0.5f * sh[0];
}

// ---------------------------------------------------------------------------
// Launch
// ---------------------------------------------------------------------------
static inline dim3 ggrid(int N) { return dim3(N / 128, MB / 128); }

extern "C" void kernel_launch(void* const* d_in, const int* in_sizes, int n_in,
                              void* d_out, int out_size)
{
    const float* x  = (const float*)d_in[0];
    const float* W0 = (const float*)d_in[1];
    const float* b0 = (const float*)d_in[2];
    const float* W1 = (const float*)d_in[3];
    const float* b1 = (const float*)d_in[4];
    const float* W2 = (const float*)d_in[5];
    const float* b2 = (const float*)d_in[6];
    float* out = (float*)d_out;

    float *r1, *r2, *r3, *e0, *e1, *e2;
    float *xr, *r1r, *r2r, *r3r, *e0r, *e1r, *e2r;
    float *w0r, *w1r, *w2r, *wt0, *wt1, *wt2, *part;
    cudaGetSymbolAddress((void**)&r1,  g_r1);
    cudaGetSymbolAddress((void**)&r2,  g_r2);
    cudaGetSymbolAddress((void**)&r3,  g_r3);
    cudaGetSymbolAddress((void**)&e0,  g_e0);
    cudaGetSymbolAddress((void**)&e1,  g_e1);
    cudaGetSymbolAddress((void**)&e2,  g_e2);
    cudaGetSymbolAddress((void**)&xr,  g_xr);
    cudaGetSymbolAddress((void**)&r1r, g_r1r);
    cudaGetSymbolAddress((void**)&r2r, g_r2r);
    cudaGetSymbolAddress((void**)&r3r, g_r3r);
    cudaGetSymbolAddress((void**)&e0r, g_e0r);
    cudaGetSymbolAddress((void**)&e1r, g_e1r);
    cudaGetSymbolAddress((void**)&e2r, g_e2r);
    cudaGetSymbolAddress((void**)&w0r, g_W0r);
    cudaGetSymbolAddress((void**)&w1r, g_W1r);
    cudaGetSymbolAddress((void**)&w2r, g_W2r);
    cudaGetSymbolAddress((void**)&wt0, g_Wt0);
    cudaGetSymbolAddress((void**)&wt1, g_Wt1);
    cudaGetSymbolAddress((void**)&wt2, g_Wt2);
    cudaGetSymbolAddress((void**)&part, g_part);

    cudaFuncSetAttribute(tc_gemm<0>, cudaFuncAttributeMaxDynamicSharedMemorySize, SMEM_SZ);
    cudaFuncSetAttribute(tc_gemm<1>, cudaFuncAttributeMaxDynamicSharedMemorySize, SMEM_SZ);
    cudaFuncSetAttribute(tc_gemm<2>, cudaFuncAttributeMaxDynamicSharedMemorySize, SMEM_SZ);

    // ---- prep: rounded (+permuted) operand copies
    roundperm_k<<<(int)(((long long)MB * D0 + 255) / 256), 256>>>(x, xr, (long long)MB * D0);
    roundperm_k<<<(int)(((long long)D1 * D0 + 255) / 256), 256>>>(W0, w0r, (long long)D1 * D0);
    roundperm_k<<<(int)(((long long)D2 * D1 + 255) / 256), 256>>>(W1, w1r, (long long)D2 * D1);
    roundperm_k<<<(int)(((long long)D3 * D2 + 255) / 256), 256>>>(W2, w2r, (long long)D3 * D2);
    transpose_rp_k<<<dim3(D0 / 32, D1 / 32), dim3(32, 8)>>>(W0, wt0, D1, D0);
    transpose_rp_k<<<dim3(D1 / 32, D2 / 32), dim3(32, 8)>>>(W1, wt1, D2, D1);
    transpose_rp_k<<<dim3(D2 / 32, D3 / 32), dim3(32, 8)>>>(W2, wt2, D3, D2);

    // ---- feedforward init: r_{i+1} = tanh(r_i @ W_i^T + b_i)
    tc_gemm<0><<<ggrid(D1), 256, SMEM_SZ>>>(xr,  w0r, b0, r1, r1r, D1, D0);
    tc_gemm<0><<<ggrid(D2), 256, SMEM_SZ>>>(r1r, w1r, b1, r2, r2r, D2, D1);
    tc_gemm<0><<<ggrid(D3), 256, SMEM_SZ>>>(r2r, w2r, b2, r3, r3r, D3, D2);

    // ---- 20 PC inference steps
    for (int s = 0; s < NSTEPS; s++) {
        // errors: e_i = r_i - tanh(r_{i+1} @ W_i)
        tc_gemm<1><<<ggrid(D2), 256, SMEM_SZ>>>(r3r, wt2, r2, e2, e2r, D2, D3);
        tc_gemm<1><<<ggrid(D1), 256, SMEM_SZ>>>(r2r, wt1, r1, e1, e1r, D1, D2);
        tc_gemm<1><<<ggrid(D0), 256, SMEM_SZ>>>(r1r, wt0, x,  e0, e0r, D0, D1);
        // updates: r_i += LR * (e_{i-1} @ W_{i-1}^T - e_i)
        tc_gemm<2><<<ggrid(D1), 256, SMEM_SZ>>>(e0r, w0r, e1, r1, r1r, D1, D0);
        tc_gemm<2><<<ggrid(D2), 256, SMEM_SZ>>>(e1r, w1r, e2, r2, r2r, D2, D1);
        tc_gemm<2><<<ggrid(D3), 256, SMEM_SZ>>>(e2r, w2r, r3, r3, r3r, D3, D2);
    }

    // ---- final errors
    tc_gemm<1><<<ggrid(D2), 256, SMEM_SZ>>>(r3r, wt2, r2, e2, e2r, D2, D3);
    tc_gemm<1><<<ggrid(D1), 256, SMEM_SZ>>>(r2r, wt1, r1, e1, e1r, D1, D2);
    tc_gemm<1><<<ggrid(D0), 256, SMEM_SZ>>>(r1r, wt0, x,  e0, e0r, D0, D1);

    // ---- output r3
    const int n_r3 = MB * D3;
    copy_k<<<(n_r3 / 4 + 255) / 256, 256>>>(r3, out, n_r3 / 4);

    // ---- total_error = 0.5 * (|e0|^2 + |e1|^2 + |e2|^2 + |r3|^2)
    sumsq_partial<<<1024, 256>>>(e0, (long long)MB * D0, part + 0);
    sumsq_partial<<<1024, 256>>>(e1, (long long)MB * D1, part + 1024);
    sumsq_partial<<<1024, 256>>>(e2, (long long)MB * D2, part + 2048);
    sumsq_partial<<<1024, 256>>>(r3, (long long)MB * D3, part + 3072);
    finalize_k<<<1, 256>>>(part, 4096, out + (out_size - 1));
}

// round 9
// speedup vs baseline: 1.2762x; 1.1071x over previous
#include <cuda_runtime.h>
#include <cstdint>
#include <math.h>

// ---------------------------------------------------------------------------
// PcLinearBlock: ARCH=(1024,2048,2048,512), BATCH=4096, STEPS=20, LR=0.1
// tf32 mma.sync m16n8k8, 128x128x32 tile, cp.async 3-stage single-sync
// pipeline. Operands pre-rounded to tf32, k-permuted (0,4,1,5,2,6,3,7) for
// 64-bit conflict-free fragment loads. Error/update phases fused: one launch
// runs 3 independent GEMMs via blockIdx routing (largest K first).
// ---------------------------------------------------------------------------

#define MB 4096
#define D0 1024
#define D1 2048
#define D2 2048
#define D3 512
#define NSTEPS 20
#define LRC 0.1f

// ---- exact fp32 state (epilogue math / reductions / output) ----
__device__ __align__(128) float g_r1[(size_t)MB * D1];
__device__ __align__(128) float g_r2[(size_t)MB * D2];
__device__ __align__(128) float g_r3[(size_t)MB * D3];
__device__ __align__(128) float g_e0[(size_t)MB * D0];
__device__ __align__(128) float g_e1[(size_t)MB * D1];
__device__ __align__(128) float g_e2[(size_t)MB * D2];
// ---- tf32-rounded, k-permuted GEMM operand shadows ----
__device__ __align__(128) float g_xr [(size_t)MB * D0];
__device__ __align__(128) float g_r1r[(size_t)MB * D1];
__device__ __align__(128) float g_r2r[(size_t)MB * D2];
__device__ __align__(128) float g_r3r[(size_t)MB * D3];
__device__ __align__(128) float g_e0r[(size_t)MB * D0];
__device__ __align__(128) float g_e1r[(size_t)MB * D1];
__device__ __align__(128) float g_e2r[(size_t)MB * D2];
__device__ __align__(128) float g_W0r[(size_t)D1 * D0];
__device__ __align__(128) float g_W1r[(size_t)D2 * D1];
__device__ __align__(128) float g_W2r[(size_t)D3 * D2];
__device__ __align__(128) float g_Wt0[(size_t)D0 * D1];
__device__ __align__(128) float g_Wt1[(size_t)D1 * D2];
__device__ __align__(128) float g_Wt2[(size_t)D2 * D3];
__device__ float g_part[4096];

// ---------------------------------------------------------------------------
// helpers
// ---------------------------------------------------------------------------
__device__ __forceinline__ uint32_t s2u(const void* p) {
    uint32_t a;
    asm("{ .reg .u64 t; cvta.to.shared.u64 t, %1; cvt.u32.u64 %0, t; }"
        : "=r"(a) : "l"(p));
    return a;
}
__device__ __forceinline__ void cp16(uint32_t dst, const void* src) {
    asm volatile("cp.async.cg.shared.global [%0], [%1], 16;"
                 :: "r"(dst), "l"(src));
}
__device__ __forceinline__ void lds2(uint32_t& x, uint32_t& y, uint32_t a) {
    asm volatile("ld.shared.v2.b32 {%0,%1}, [%2];"
                 : "=r"(x), "=r"(y) : "r"(a));
}
__device__ __forceinline__ float rnd_tf32(float f) {
    uint32_t u;
    asm("cvt.rna.tf32.f32 %0, %1;" : "=r"(u) : "f"(f));
    return __uint_as_float(u);
}
__device__ __forceinline__ void mma8(float* c, const uint32_t* a,
                                     const uint32_t* b) {
    asm volatile(
        "mma.sync.aligned.m16n8k8.row.col.f32.tf32.tf32.f32 "
        "{%0,%1,%2,%3}, {%4,%5,%6,%7}, {%8,%9}, {%0,%1,%2,%3};"
        : "+f"(c[0]), "+f"(c[1]), "+f"(c[2]), "+f"(c[3])
        : "r"(a[0]), "r"(a[1]), "r"(a[2]), "r"(a[3]), "r"(b[0]), "r"(b[1]));
}
__device__ __forceinline__ float fast_tanh(float x) {
    float e = __expf(2.0f * x);
    return 1.0f - 2.0f / (e + 1.0f);
}
// permute k within 8-group to (0,4,1,5,2,6,3,7): p(j) = ((j&3)<<1)|(j>>2)
__device__ __forceinline__ int perm8(int j) {
    return ((j & 3) << 1) | ((j >> 2) & 1);
}

// ---------------------------------------------------------------------------
// GEMM body:  C[m,n] = sum_k A[m,k]*B[n,k]   (tf32-rounded, k-permuted ops)
// 128x128x32 tile, 256 thr, 3-stage cp.async, ONE __syncthreads per chunk.
// EPI 0: D = tanh(acc + X[n]);  EPI 1: D = X - tanh(acc);
// EPI 2: D += LR*(acc - X).   Writes exact D and rounded+permuted Dr.
// ---------------------------------------------------------------------------
#define STG_B   32768
#define SMEM_SZ (3 * STG_B)

template <int EPI>
__device__ __forceinline__ void gemm_body(
    const float* __restrict__ A, const float* __restrict__ B,
    const float* __restrict__ X, float* __restrict__ D,
    float* __restrict__ Dr, int N, int K, int bm, int bn, char* smem)
{
    const uint32_t sb = s2u(smem);
    const int tid = threadIdx.x;
    const int wid = tid >> 5, lane = tid & 31;
    const int gid = lane >> 2, tig = lane & 3;
    const int warp_m = wid & 1;
    const int warp_n = wid >> 1;

    // global->smem: thread t copies 64B of row t/2 (16B chunks, swizzled)
    const int ar = tid >> 1;
    const int half = tid & 1;
    const float* gA = A + (size_t)(bm + ar) * K + half * 16;
    const float* gB = B + (size_t)(bn + ar) * K + half * 16;
    uint32_t sw[4];
#pragma unroll
    for (int i = 0; i < 4; i++) {
        int cc = half * 4 + i;
        sw[i] = (uint32_t)(ar * 128 + ((cc ^ (2 * (ar & 3))) * 16));
    }

    const int KT = K >> 5;

    // ---- prologue: stages 0,1 (prefetch depth 2)
#pragma unroll
    for (int kt = 0; kt < 2; kt++) {
        uint32_t base = sb + kt * STG_B;
        const float* pa = gA + kt * 32;
        const float* pb = gB + kt * 32;
#pragma unroll
        for (int i = 0; i < 4; i++) cp16(base + sw[i], pa + i * 4);
#pragma unroll
        for (int i = 0; i < 4; i++) cp16(base + 16384 + sw[i], pb + i * 4);
        asm volatile("cp.async.commit_group;" ::: "memory");
    }

    float acc[4][4][4];
#pragma unroll
    for (int mi = 0; mi < 4; mi++)
#pragma unroll
        for (int ni = 0; ni < 4; ni++)
#pragma unroll
            for (int r = 0; r < 4; r++) acc[mi][ni][r] = 0.f;

    const int g3 = gid & 3;

    // ---- mainloop: one barrier per chunk
    for (int kt = 0; kt < KT; kt++) {
        // all of load(<=kt) complete for this thread, then make visible
        asm volatile("cp.async.wait_group 1;" ::: "memory");
        __syncthreads();
        // after barrier every warp finished compute(kt-1) -> buffer
        // (kt+2)%3 == (kt-1)%3 is free; issue next loads, then compute.
        const int kn = kt + 2;
        if (kn < KT) {
            uint32_t base = sb + (kn % 3) * STG_B;
            const float* pa = gA + kn * 32;
            const float* pb = gB + kn * 32;
#pragma unroll
            for (int i = 0; i < 4; i++) cp16(base + sw[i], pa + i * 4);
#pragma unroll
            for (int i = 0; i < 4; i++) cp16(base + 16384 + sw[i], pb + i * 4);
        }
        asm volatile("cp.async.commit_group;" ::: "memory");

        const uint32_t sA = sb + (kt % 3) * STG_B;
        const uint32_t sB = sA + 16384;

#pragma unroll
        for (int ks = 0; ks < 4; ks++) {
            const uint32_t coloff = (uint32_t)(32 * (ks ^ g3) + 8 * tig);
            uint32_t a[4][4], b[4][2];
#pragma unroll
            for (int mi = 0; mi < 4; mi++) {
                uint32_t ad = sA +
                    (uint32_t)((warp_m * 64 + mi * 16 + gid) * 128) + coloff;
                lds2(a[mi][0], a[mi][2], ad);
                lds2(a[mi][1], a[mi][3], ad + 1024);   // +8 rows
            }
#pragma unroll
            for (int ni = 0; ni < 4; ni++) {
                uint32_t bd = sB +
                    (uint32_t)((warp_n * 32 + ni * 8 + gid) * 128) + coloff;
                lds2(b[ni][0], b[ni][1], bd);
            }
#pragma unroll
            for (int mi = 0; mi < 4; mi++)
#pragma unroll
                for (int ni = 0; ni < 4; ni++)
                    mma8(acc[mi][ni], a[mi], b[ni]);
        }
    }

    // ---- fused epilogue: exact store + rounded/permuted shadow store
#pragma unroll
    for (int mi = 0; mi < 4; mi++) {
        const int gm = bm + warp_m * 64 + mi * 16 + gid;
#pragma unroll
        for (int ni = 0; ni < 4; ni++) {
            const int gn = bn + warp_n * 32 + ni * 8 + 2 * tig;
            const size_t i0 = (size_t)gm * N + gn;
            const size_t i1 = i0 + (size_t)8 * N;
            const float* c = acc[mi][ni];
            float2 o0, o1;
            if (EPI == 0) {
                float b0v = X[gn], b1v = X[gn + 1];
                o0.x = fast_tanh(c[0] + b0v);
                o0.y = fast_tanh(c[1] + b1v);
                o1.x = fast_tanh(c[2] + b0v);
                o1.y = fast_tanh(c[3] + b1v);
            } else if (EPI == 1) {
                float2 x0 = *reinterpret_cast<const float2*>(&X[i0]);
                float2 x1 = *reinterpret_cast<const float2*>(&X[i1]);
                o0.x = x0.x - fast_tanh(c[0]);
                o0.y = x0.y - fast_tanh(c[1]);
                o1.x = x1.x - fast_tanh(c[2]);
                o1.y = x1.y - fast_tanh(c[3]);
            } else {
                float2 x0 = *reinterpret_cast<const float2*>(&X[i0]);
                float2 x1 = *reinterpret_cast<const float2*>(&X[i1]);
                float2 d0 = *reinterpret_cast<const float2*>(&D[i0]);
                float2 d1 = *reinterpret_cast<const float2*>(&D[i1]);
                o0.x = d0.x + LRC * (c[0] - x0.x);
                o0.y = d0.y + LRC * (c[1] - x0.y);
                o1.x = d1.x + LRC * (c[2] - x1.x);
                o1.y = d1.y + LRC * (c[3] - x1.y);
            }
            *reinterpret_cast<float2*>(&D[i0]) = o0;
            *reinterpret_cast<float2*>(&D[i1]) = o1;
            const int nb = gn & ~7;
            const int p0 = nb + perm8(gn & 7);
            const int p1 = nb + perm8((gn + 1) & 7);
            const size_t rowr0 = (size_t)gm * N;
            const size_t rowr1 = rowr0 + (size_t)8 * N;
            Dr[rowr0 + p0] = rnd_tf32(o0.x);
            Dr[rowr0 + p1] = rnd_tf32(o0.y);
            Dr[rowr1 + p0] = rnd_tf32(o1.x);
            Dr[rowr1 + p1] = rnd_tf32(o1.y);
        }
    }
}

// ---- single-GEMM kernel (feedforward) ----
template <int EPI>
__global__ void __launch_bounds__(256, 2)
tc_gemm(const float* __restrict__ A, const float* __restrict__ B,
        const float* __restrict__ X, float* __restrict__ D,
        float* __restrict__ Dr, int N, int K)
{
    extern __shared__ char smem[];
    gemm_body<EPI>(A, B, X, D, Dr, N, K,
                   blockIdx.y * 128, blockIdx.x * 128, smem);
}

// ---- fused 3-GEMM kernel (error / update phases) ----
struct Sub {
    const float* A; const float* B; const float* X;
    float* D; float* Dr; int N; int K;
};

template <int EPI>
__global__ void __launch_bounds__(256, 2)
tc_gemm3(Sub s0, Sub s1, Sub s2, int t0, int t1)
{
    extern __shared__ char smem[];
    const int bx = blockIdx.x;
    const float *A, *B, *X; float *D, *Dr; int N, K, bn;
    if (bx < t0)      { A=s0.A; B=s0.B; X=s0.X; D=s0.D; Dr=s0.Dr;
                        N=s0.N; K=s0.K; bn = bx * 128; }
    else if (bx < t1) { A=s1.A; B=s1.B; X=s1.X; D=s1.D; Dr=s1.Dr;
                        N=s1.N; K=s1.K; bn = (bx - t0) * 128; }
    else              { A=s2.A; B=s2.B; X=s2.X; D=s2.D; Dr=s2.Dr;
                        N=s2.N; K=s2.K; bn = (bx - t1) * 128; }
    gemm_body<EPI>(A, B, X, D, Dr, N, K, blockIdx.y * 128, bn, smem);
}

// ---------------------------------------------------------------------------
// prep kernels
// ---------------------------------------------------------------------------
__global__ void roundperm_k(const float* __restrict__ src,
                            float* __restrict__ dst, long long n)
{
    long long i = (long long)blockIdx.x * blockDim.x + threadIdx.x;
    if (i < n) {
        long long base = i & ~7LL;
        int j = (int)(i & 7);
        dst[base + perm8(j)] = rnd_tf32(src[i]);
    }
}

__global__ void transpose_rp_k(const float* __restrict__ src,
                               float* __restrict__ dst, int R, int C)
{
    __shared__ float t[32][33];
    int bx = blockIdx.x * 32, by = blockIdx.y * 32;
    int x = bx + threadIdx.x;
#pragma unroll
    for (int i = 0; i < 32; i += 8)
        t[threadIdx.y + i][threadIdx.x] =
            src[(size_t)(by + threadIdx.y + i) * C + x];
    __syncthreads();
    int xo = by + threadIdx.x;
    int xp = (xo & ~7) | perm8(xo & 7);
#pragma unroll
    for (int i = 0; i < 32; i += 8)
        dst[(size_t)(bx + threadIdx.y + i) * R + xp] =
            rnd_tf32(t[threadIdx.x][threadIdx.y + i]);
}

// ---------------------------------------------------------------------------
// output copy + deterministic two-stage sum-of-squares
// ---------------------------------------------------------------------------
__global__ void copy_k(const float* __restrict__ s, float* __restrict__ d,
                       int n4)
{
    int i = blockIdx.x * blockDim.x + threadIdx.x;
    if (i < n4)
        reinterpret_cast<float4*>(d)[i] =
            reinterpret_cast<const float4*>(s)[i];
}

__global__ void sumsq_partial(const float* __restrict__ x, long long n,
                              float* __restrict__ part)
{
    float s = 0.f;
    long long stride = (long long)gridDim.x * blockDim.x;
    for (long long i = (long long)blockIdx.x * blockDim.x + threadIdx.x;
         i < n; i += stride) {
        float v = x[i];
        s = fmaf(v, v, s);
    }
    __shared__ float sh[256];
    sh[threadIdx.x] = s;
    __syncthreads();
    for (int o = 128; o > 0; o >>= 1) {
        if (threadIdx.x < o) sh[threadIdx.x] += sh[threadIdx.x + o];
        __syncthreads();
    }
    if (threadIdx.x == 0) part[blockIdx.x] = sh[0];
}

__global__ void finalize_k(const float* __restrict__ part, int n,
                           float* __restrict__ out)
{
    float s = 0.f;
    for (int i = threadIdx.x; i < n; i += 256) s += part[i];
    __shared__ float sh[256];
    sh[threadIdx.x] = s;
    __syncthreads();
    for (int o = 128; o > 0; o >>= 1) {
        if (threadIdx.x < o) sh[threadIdx.x] += sh[threadIdx.x + o];
        __syncthreads();
    }
    if (threadIdx.x == 0) out[0] = 0.5f * sh[0];
}

// ---------------------------------------------------------------------------
// Launch
// ---------------------------------------------------------------------------
static inline dim3 ggrid(int N) { return dim3(N / 128, MB / 128); }

extern "C" void kernel_launch(void* const* d_in, const int* in_sizes, int n_in,
                              void* d_out, int out_size)
{
    const float* x  = (const float*)d_in[0];
    const float* W0 = (const float*)d_in[1];
    const float* b0 = (const float*)d_in[2];
    const float* W1 = (const float*)d_in[3];
    const float* b1 = (const float*)d_in[4];
    const float* W2 = (const float*)d_in[5];
    const float* b2 = (const float*)d_in[6];
    float* out = (float*)d_out;

    float *r1, *r2, *r3, *e0, *e1, *e2;
    float *xr, *r1r, *r2r, *r3r, *e0r, *e1r, *e2r;
    float *w0r, *w1r, *w2r, *wt0, *wt1, *wt2, *part;
    cudaGetSymbolAddress((void**)&r1,  g_r1);
    cudaGetSymbolAddress((void**)&r2,  g_r2);
    cudaGetSymbolAddress((void**)&r3,  g_r3);
    cudaGetSymbolAddress((void**)&e0,  g_e0);
    cudaGetSymbolAddress((void**)&e1,  g_e1);
    cudaGetSymbolAddress((void**)&e2,  g_e2);
    cudaGetSymbolAddress((void**)&xr,  g_xr);
    cudaGetSymbolAddress((void**)&r1r, g_r1r);
    cudaGetSymbolAddress((void**)&r2r, g_r2r);
    cudaGetSymbolAddress((void**)&r3r, g_r3r);
    cudaGetSymbolAddress((void**)&e0r, g_e0r);
    cudaGetSymbolAddress((void**)&e1r, g_e1r);
    cudaGetSymbolAddress((void**)&e2r, g_e2r);
    cudaGetSymbolAddress((void**)&w0r, g_W0r);
    cudaGetSymbolAddress((void**)&w1r, g_W1r);
    cudaGetSymbolAddress((void**)&w2r, g_W2r);
    cudaGetSymbolAddress((void**)&wt0, g_Wt0);
    cudaGetSymbolAddress((void**)&wt1, g_Wt1);
    cudaGetSymbolAddress((void**)&wt2, g_Wt2);
    cudaGetSymbolAddress((void**)&part, g_part);

    cudaFuncSetAttribute(tc_gemm<0>,  cudaFuncAttributeMaxDynamicSharedMemorySize, SMEM_SZ);
    cudaFuncSetAttribute(tc_gemm3<1>, cudaFuncAttributeMaxDynamicSharedMemorySize, SMEM_SZ);
    cudaFuncSetAttribute(tc_gemm3<2>, cudaFuncAttributeMaxDynamicSharedMemorySize, SMEM_SZ);

    // ---- prep: rounded (+permuted) operand copies
    roundperm_k<<<(int)(((long long)MB * D0 + 255) / 256), 256>>>(x, xr, (long long)MB * D0);
    roundperm_k<<<(int)(((long long)D1 * D0 + 255) / 256), 256>>>(W0, w0r, (long long)D1 * D0);
    roundperm_k<<<(int)(((long long)D2 * D1 + 255) / 256), 256>>>(W1, w1r, (long long)D2 * D1);
    roundperm_k<<<(int)(((long long)D3 * D2 + 255) / 256), 256>>>(W2, w2r, (long long)D3 * D2);
    transpose_rp_k<<<dim3(D0 / 32, D1 / 32), dim3(32, 8)>>>(W0, wt0, D1, D0);
    transpose_rp_k<<<dim3(D1 / 32, D2 / 32), dim3(32, 8)>>>(W1, wt1, D2, D1);
    transpose_rp_k<<<dim3(D2 / 32, D3 / 32), dim3(32, 8)>>>(W2, wt2, D3, D2);

    // ---- feedforward init: r_{i+1} = tanh(r_i @ W_i^T + b_i)
    tc_gemm<0><<<ggrid(D1), 256, SMEM_SZ>>>(xr,  w0r, b0, r1, r1r, D1, D0);
    tc_gemm<0><<<ggrid(D2), 256, SMEM_SZ>>>(r1r, w1r, b1, r2, r2r, D2, D1);
    tc_gemm<0><<<ggrid(D3), 256, SMEM_SZ>>>(r2r, w2r, b2, r3, r3r, D3, D2);

    // ---- fused phase descriptors (largest K first)
    Sub se1 = { r2r, wt1, r1, e1, e1r, D1, D2 };   // 16 tiles, K=2048
    Sub se0 = { r1r, wt0, x,  e0, e0r, D0, D1 };   // 8 tiles,  K=2048
    Sub se2 = { r3r, wt2, r2, e2, e2r, D2, D3 };   // 16 tiles, K=512
    Sub su2 = { e1r, w1r, e2, r2, r2r, D2, D1 };   // 16 tiles, K=2048
    Sub su3 = { e2r, w2r, r3, r3, r3r, D3, D2 };   // 4 tiles,  K=2048
    Sub su1 = { e0r, w0r, e1, r1, r1r, D1, D0 };   // 16 tiles, K=1024

    const dim3 gerr(16 + 8 + 16, MB / 128);
    const dim3 gupd(16 + 4 + 16, MB / 128);

    // ---- 20 PC inference steps: 2 launches per step
    for (int s = 0; s < NSTEPS; s++) {
        tc_gemm3<1><<<gerr, 256, SMEM_SZ>>>(se1, se0, se2, 16, 24);
        tc_gemm3<2><<<gupd, 256, SMEM_SZ>>>(su2, su3, su1, 16, 20);
    }

    // ---- final errors (fused)
    tc_gemm3<1><<<gerr, 256, SMEM_SZ>>>(se1, se0, se2, 16, 24);

    // ---- output r3
    const int n_r3 = MB * D3;
    copy_k<<<(n_r3 / 4 + 255) / 256, 256>>>(r3, out, n_r3 / 4);

    // ---- total_error = 0.5 * (|e0|^2 + |e1|^2 + |e2|^2 + |r3|^2)
    sumsq_partial<<<1024, 256>>>(e0, (long long)MB * D0, part + 0);
    sumsq_partial<<<1024, 256>>>(e1, (long long)MB * D1, part + 1024);
    sumsq_partial<<<1024, 256>>>(e2, (long long)MB * D2, part + 2048);
    sumsq_partial<<<1024, 256>>>(r3, (long long)MB * D3, part + 3072);
    finalize_k<<<1, 256>>>(part, 4096, out + (out_size - 1));
}

// round 10
// speedup vs baseline: 2.3806x; 1.8653x over previous
#include <cuda_runtime.h>
#include <cuda_fp16.h>
#include <cstdint>
#include <math.h>

// ---------------------------------------------------------------------------
// PcLinearBlock: ARCH=(1024,2048,2048,512), BATCH=4096, STEPS=20, LR=0.1
// fp16 mma.sync m16n8k16 (same 10-bit mantissa as tf32, 2x K and 2x rate),
// fp32 accumulate. 128x128x64 tile, cp.async 3-stage single-sync pipeline.
// Operands pre-rounded to fp16, k-PAIR-permuted (0,4,1,5,2,6,3,7) so one
// ld.shared.v2.b32 yields the (k-lo, k-hi) fragment pair, conflict-free.
// Exact fp32 state arrays carry all epilogue math / reductions / output.
// Error/update phases fused into single launches via blockIdx routing.
// ---------------------------------------------------------------------------

#define MB 4096
#define D0 1024
#define D1 2048
#define D2 2048
#define D3 512
#define NSTEPS 20
#define LRC 0.1f

// ---- exact fp32 state ----
__device__ __align__(128) float g_r1[(size_t)MB * D1];
__device__ __align__(128) float g_r2[(size_t)MB * D2];
__device__ __align__(128) float g_r3[(size_t)MB * D3];
__device__ __align__(128) float g_e0[(size_t)MB * D0];
__device__ __align__(128) float g_e1[(size_t)MB * D1];
__device__ __align__(128) float g_e2[(size_t)MB * D2];
// ---- fp16-rounded, pair-permuted GEMM operand shadows ----
__device__ __align__(128) __half g_xr [(size_t)MB * D0];
__device__ __align__(128) __half g_r1r[(size_t)MB * D1];
__device__ __align__(128) __half g_r2r[(size_t)MB * D2];
__device__ __align__(128) __half g_r3r[(size_t)MB * D3];
__device__ __align__(128) __half g_e0r[(size_t)MB * D0];
__device__ __align__(128) __half g_e1r[(size_t)MB * D1];
__device__ __align__(128) __half g_e2r[(size_t)MB * D2];
__device__ __align__(128) __half g_W0r[(size_t)D1 * D0];
__device__ __align__(128) __half g_W1r[(size_t)D2 * D1];
__device__ __align__(128) __half g_W2r[(size_t)D3 * D2];
__device__ __align__(128) __half g_Wt0[(size_t)D0 * D1];
__device__ __align__(128) __half g_Wt1[(size_t)D1 * D2];
__device__ __align__(128) __half g_Wt2[(size_t)D2 * D3];
__device__ float g_part[4096];

// ---------------------------------------------------------------------------
// helpers
// ---------------------------------------------------------------------------
__device__ __forceinline__ uint32_t s2u(const void* p) {
    uint32_t a;
    asm("{ .reg .u64 t; cvta.to.shared.u64 t, %1; cvt.u32.u64 %0, t; }"
        : "=r"(a) : "l"(p));
    return a;
}
__device__ __forceinline__ void cp16(uint32_t dst, const void* src) {
    asm volatile("cp.async.cg.shared.global [%0], [%1], 16;"
                 :: "r"(dst), "l"(src));
}
__device__ __forceinline__ void lds2(uint32_t& x, uint32_t& y, uint32_t a) {
    asm volatile("ld.shared.v2.b32 {%0,%1}, [%2];"
                 : "=r"(x), "=r"(y) : "r"(a));
}
__device__ __forceinline__ void mma16(float* c, const uint32_t* a,
                                      const uint32_t* b) {
    asm volatile(
        "mma.sync.aligned.m16n8k16.row.col.f32.f16.f16.f32 "
        "{%0,%1,%2,%3}, {%4,%5,%6,%7}, {%8,%9}, {%0,%1,%2,%3};"
        : "+f"(c[0]), "+f"(c[1]), "+f"(c[2]), "+f"(c[3])
        : "r"(a[0]), "r"(a[1]), "r"(a[2]), "r"(a[3]), "r"(b[0]), "r"(b[1]));
}
__device__ __forceinline__ float fast_tanh(float x) {
    float e = __expf(2.0f * x);
    return 1.0f - 2.0f / (e + 1.0f);
}
// permute pair-index within 8 to (0,4,1,5,2,6,3,7)
__device__ __forceinline__ int perm8(int j) {
    return ((j & 3) << 1) | ((j >> 2) & 1);
}

// ---------------------------------------------------------------------------
// GEMM body:  C[m,n] = sum_k A[m,k]*B[n,k]   (fp16 ops, pair-permuted k)
// 128x128x64 tile, 256 thr, 3-stage cp.async, ONE __syncthreads per chunk.
// EPI 0: D = tanh(acc + X[n]);  EPI 1: D = X - tanh(acc);
// EPI 2: D += LR*(acc - X).   Writes exact fp32 D and fp16 shadow Dr.
// ---------------------------------------------------------------------------
#define STG_B   32768            // A 16KB + B 16KB (128 rows x 128B each)
#define SMEM_SZ (3 * STG_B)

template <int EPI>
__device__ __forceinline__ void gemm_body(
    const __half* __restrict__ A, const __half* __restrict__ B,
    const float* __restrict__ X, float* __restrict__ D,
    __half* __restrict__ Dr, int N, int K, int bm, int bn, char* smem)
{
    const uint32_t sb = s2u(smem);
    const int tid = threadIdx.x;
    const int wid = tid >> 5, lane = tid & 31;
    const int gid = lane >> 2, tig = lane & 3;
    const int warp_m = wid & 1;
    const int warp_n = wid >> 1;

    // global->smem: thread t copies 64B of row t/2 (16B chunks, swizzled)
    const int ar = tid >> 1;
    const int half = tid & 1;
    const __half* gA = A + (size_t)(bm + ar) * K + half * 32;
    const __half* gB = B + (size_t)(bn + ar) * K + half * 32;
    uint32_t sw[4];
#pragma unroll
    for (int i = 0; i < 4; i++) {
        int cc = half * 4 + i;
        sw[i] = (uint32_t)(ar * 128 + ((cc ^ (2 * (ar & 3))) * 16));
    }

    const int KT = K >> 6;            // 64 fp16 per chunk = 128B row

    // ---- prologue: stages 0,1
#pragma unroll
    for (int kt = 0; kt < 2; kt++) {
        uint32_t base = sb + kt * STG_B;
        const __half* pa = gA + kt * 64;
        const __half* pb = gB + kt * 64;
#pragma unroll
        for (int i = 0; i < 4; i++) cp16(base + sw[i], pa + i * 8);
#pragma unroll
        for (int i = 0; i < 4; i++) cp16(base + 16384 + sw[i], pb + i * 8);
        asm volatile("cp.async.commit_group;" ::: "memory");
    }

    float acc[4][4][4];
#pragma unroll
    for (int mi = 0; mi < 4; mi++)
#pragma unroll
        for (int ni = 0; ni < 4; ni++)
#pragma unroll
            for (int r = 0; r < 4; r++) acc[mi][ni][r] = 0.f;

    const int g3 = gid & 3;

    // ---- mainloop: one barrier per 64-k chunk
    for (int kt = 0; kt < KT; kt++) {
        asm volatile("cp.async.wait_group 1;" ::: "memory");
        __syncthreads();
        const int kn = kt + 2;
        if (kn < KT) {
            uint32_t base = sb + (kn % 3) * STG_B;
            const __half* pa = gA + kn * 64;
            const __half* pb = gB + kn * 64;
#pragma unroll
            for (int i = 0; i < 4; i++) cp16(base + sw[i], pa + i * 8);
#pragma unroll
            for (int i = 0; i < 4; i++) cp16(base + 16384 + sw[i], pb + i * 8);
        }
        asm volatile("cp.async.commit_group;" ::: "memory");

        const uint32_t sA = sb + (kt % 3) * STG_B;
        const uint32_t sB = sA + 16384;

#pragma unroll
        for (int ks = 0; ks < 4; ks++) {            // 4 x k16 per chunk
            const uint32_t coloff = (uint32_t)(32 * (ks ^ g3) + 8 * tig);
            uint32_t a[4][4], b[4][2];
#pragma unroll
            for (int mi = 0; mi < 4; mi++) {
                uint32_t ad = sA +
                    (uint32_t)((warp_m * 64 + mi * 16 + gid) * 128) + coloff;
                lds2(a[mi][0], a[mi][2], ad);          // row gid: k-lo, k-hi
                lds2(a[mi][1], a[mi][3], ad + 1024);   // row gid+8
            }
#pragma unroll
            for (int ni = 0; ni < 4; ni++) {
                uint32_t bd = sB +
                    (uint32_t)((warp_n * 32 + ni * 8 + gid) * 128) + coloff;
                lds2(b[ni][0], b[ni][1], bd);
            }
#pragma unroll
            for (int mi = 0; mi < 4; mi++)
#pragma unroll
                for (int ni = 0; ni < 4; ni++)
                    mma16(acc[mi][ni], a[mi], b[ni]);
        }
    }

    // ---- fused epilogue: exact fp32 store + fp16 pair-permuted shadow
#pragma unroll
    for (int mi = 0; mi < 4; mi++) {
        const int gm = bm + warp_m * 64 + mi * 16 + gid;
#pragma unroll
        for (int ni = 0; ni < 4; ni++) {
            const int gn = bn + warp_n * 32 + ni * 8 + 2 * tig;   // even
            const size_t i0 = (size_t)gm * N + gn;
            const size_t i1 = i0 + (size_t)8 * N;
            const float* c = acc[mi][ni];
            float2 o0, o1;
            if (EPI == 0) {
                float b0v = X[gn], b1v = X[gn + 1];
                o0.x = fast_tanh(c[0] + b0v);
                o0.y = fast_tanh(c[1] + b1v);
                o1.x = fast_tanh(c[2] + b0v);
                o1.y = fast_tanh(c[3] + b1v);
            } else if (EPI == 1) {
                float2 x0 = *reinterpret_cast<const float2*>(&X[i0]);
                float2 x1 = *reinterpret_cast<const float2*>(&X[i1]);
                o0.x = x0.x - fast_tanh(c[0]);
                o0.y = x0.y - fast_tanh(c[1]);
                o1.x = x1.x - fast_tanh(c[2]);
                o1.y = x1.y - fast_tanh(c[3]);
            } else {
                float2 x0 = *reinterpret_cast<const float2*>(&X[i0]);
                float2 x1 = *reinterpret_cast<const float2*>(&X[i1]);
                float2 d0 = *reinterpret_cast<const float2*>(&D[i0]);
                float2 d1 = *reinterpret_cast<const float2*>(&D[i1]);
                o0.x = d0.x + LRC * (c[0] - x0.x);
                o0.y = d0.y + LRC * (c[1] - x0.y);
                o1.x = d1.x + LRC * (c[2] - x1.x);
                o1.y = d1.y + LRC * (c[3] - x1.y);
            }
            *reinterpret_cast<float2*>(&D[i0]) = o0;
            *reinterpret_cast<float2*>(&D[i1]) = o1;
            // fp16 shadow: pair-permute within 16-col groups
            const int pos = (gn & ~15) + 2 * perm8((gn >> 1) & 7);
            const size_t rowr0 = (size_t)gm * N;
            const size_t rowr1 = rowr0 + (size_t)8 * N;
            *reinterpret_cast<__half2*>(&Dr[rowr0 + pos]) =
                __halves2half2(__float2half_rn(o0.x), __float2half_rn(o0.y));
            *reinterpret_cast<__half2*>(&Dr[rowr1 + pos]) =
                __halves2half2(__float2half_rn(o1.x), __float2half_rn(o1.y));
        }
    }
}

// ---- single-GEMM kernel (feedforward) ----
template <int EPI>
__global__ void __launch_bounds__(256, 2)
tc_gemm(const __half* __restrict__ A, const __half* __restrict__ B,
        const float* __restrict__ X, float* __restrict__ D,
        __half* __restrict__ Dr, int N, int K)
{
    extern __shared__ char smem[];
    gemm_body<EPI>(A, B, X, D, Dr, N, K,
                   blockIdx.y * 128, blockIdx.x * 128, smem);
}

// ---- fused 3-GEMM kernel (error / update phases) ----
struct Sub {
    const __half* A; const __half* B; const float* X;
    float* D; __half* Dr; int N; int K;
};

template <int EPI>
__global__ void __launch_bounds__(256, 2)
tc_gemm3(Sub s0, Sub s1, Sub s2, int t0, int t1)
{
    extern __shared__ char smem[];
    const int bx = blockIdx.x;
    const __half *A, *B; const float* X; float* D; __half* Dr; int N, K, bn;
    if (bx < t0)      { A=s0.A; B=s0.B; X=s0.X; D=s0.D; Dr=s0.Dr;
                        N=s0.N; K=s0.K; bn = bx * 128; }
    else if (bx < t1) { A=s1.A; B=s1.B; X=s1.X; D=s1.D; Dr=s1.Dr;
                        N=s1.N; K=s1.K; bn = (bx - t0) * 128; }
    else              { A=s2.A; B=s2.B; X=s2.X; D=s2.D; Dr=s2.Dr;
                        N=s2.N; K=s2.K; bn = (bx - t1) * 128; }
    gemm_body<EPI>(A, B, X, D, Dr, N, K, blockIdx.y * 128, bn, smem);
}

// ---------------------------------------------------------------------------
// prep kernels: fp32 -> fp16 with pair-permutation (and transpose for Wt)
// ---------------------------------------------------------------------------
__global__ void roundperm_h(const float* __restrict__ src,
                            __half* __restrict__ dst, long long n)
{
    long long i = (long long)blockIdx.x * blockDim.x + threadIdx.x;
    if (i < n) {
        int j = (int)((i >> 1) & 7);
        long long pos = (i & ~15LL) + 2 * perm8(j) + (i & 1);
        dst[pos] = __float2half_rn(src[i]);
    }
}

__global__ void transpose_rp_h(const float* __restrict__ src,
                               __half* __restrict__ dst, int R, int C)
{
    __shared__ float t[32][33];
    int bx = blockIdx.x * 32, by = blockIdx.y * 32;
    int x = bx + threadIdx.x;
#pragma unroll
    for (int i = 0; i < 32; i += 8)
        t[threadIdx.y + i][threadIdx.x] =
            src[(size_t)(by + threadIdx.y + i) * C + x];
    __syncthreads();
    int xo = by + threadIdx.x;
    int xp = (xo & ~15) + 2 * perm8((xo >> 1) & 7) + (xo & 1);
#pragma unroll
    for (int i = 0; i < 32; i += 8)
        dst[(size_t)(bx + threadIdx.y + i) * R + xp] =
            __float2half_rn(t[threadIdx.x][threadIdx.y + i]);
}

// ---------------------------------------------------------------------------
// output copy + deterministic two-stage sum-of-squares
// ---------------------------------------------------------------------------
__global__ void copy_k(const float* __restrict__ s, float* __restrict__ d,
                       int n4)
{
    int i = blockIdx.x * blockDim.x + threadIdx.x;
    if (i < n4)
        reinterpret_cast<float4*>(d)[i] =
            reinterpret_cast<const float4*>(s)[i];
}

__global__ void sumsq_partial(const float* __restrict__ x, long long n,
                              float* __restrict__ part)
{
    float s = 0.f;
    long long stride = (long long)gridDim.x * blockDim.x;
    for (long long i = (long long)blockIdx.x * blockDim.x + threadIdx.x;
         i < n; i += stride) {
        float v = x[i];
        s = fmaf(v, v, s);
    }
    __shared__ float sh[256];
    sh[threadIdx.x] = s;
    __syncthreads();
    for (int o = 128; o > 0; o >>= 1) {
        if (threadIdx.x < o) sh[threadIdx.x] += sh[threadIdx.x + o];
        __syncthreads();
    }
    if (threadIdx.x == 0) part[blockIdx.x] = sh[0];
}

__global__ void finalize_k(const float* __restrict__ part, int n,
                           float* __restrict__ out)
{
    float s = 0.f;
    for (int i = threadIdx.x; i < n; i += 256) s += part[i];
    __shared__ float sh[256];
    sh[threadIdx.x] = s;
    __syncthreads();
    for (int o = 128; o > 0; o >>= 1) {
        if (threadIdx.x < o) sh[threadIdx.x] += sh[threadIdx.x + o];
        __syncthreads();
    }
    if (threadIdx.x == 0) out[0] = 0.5f * sh[0];
}

// ---------------------------------------------------------------------------
// Launch
// ---------------------------------------------------------------------------
static inline dim3 ggrid(int N) { return dim3(N / 128, MB / 128); }

extern "C" void kernel_launch(void* const* d_in, const int* in_sizes, int n_in,
                              void* d_out, int out_size)
{
    const float* x  = (const float*)d_in[0];
    const float* W0 = (const float*)d_in[1];
    const float* b0 = (const float*)d_in[2];
    const float* W1 = (const float*)d_in[3];
    const float* b1 = (const float*)d_in[4];
    const float* W2 = (const float*)d_in[5];
    const float* b2 = (const float*)d_in[6];
    float* out = (float*)d_out;

    float *r1, *r2, *r3, *e0, *e1, *e2, *part;
    __half *xr, *r1r, *r2r, *r3r, *e0r, *e1r, *e2r;
    __half *w0r, *w1r, *w2r, *wt0, *wt1, *wt2;
    cudaGetSymbolAddress((void**)&r1,  g_r1);
    cudaGetSymbolAddress((void**)&r2,  g_r2);
    cudaGetSymbolAddress((void**)&r3,  g_r3);
    cudaGetSymbolAddress((void**)&e0,  g_e0);
    cudaGetSymbolAddress((void**)&e1,  g_e1);
    cudaGetSymbolAddress((void**)&e2,  g_e2);
    cudaGetSymbolAddress((void**)&xr,  g_xr);
    cudaGetSymbolAddress((void**)&r1r, g_r1r);
    cudaGetSymbolAddress((void**)&r2r, g_r2r);
    cudaGetSymbolAddress((void**)&r3r, g_r3r);
    cudaGetSymbolAddress((void**)&e0r, g_e0r);
    cudaGetSymbolAddress((void**)&e1r, g_e1r);
    cudaGetSymbolAddress((void**)&e2r, g_e2r);
    cudaGetSymbolAddress((void**)&w0r, g_W0r);
    cudaGetSymbolAddress((void**)&w1r, g_W1r);
    cudaGetSymbolAddress((void**)&w2r, g_W2r);
    cudaGetSymbolAddress((void**)&wt0, g_Wt0);
    cudaGetSymbolAddress((void**)&wt1, g_Wt1);
    cudaGetSymbolAddress((void**)&wt2, g_Wt2);
    cudaGetSymbolAddress((void**)&part, g_part);

    cudaFuncSetAttribute(tc_gemm<0>,  cudaFuncAttributeMaxDynamicSharedMemorySize, SMEM_SZ);
    cudaFuncSetAttribute(tc_gemm3<1>, cudaFuncAttributeMaxDynamicSharedMemorySize, SMEM_SZ);
    cudaFuncSetAttribute(tc_gemm3<2>, cudaFuncAttributeMaxDynamicSharedMemorySize, SMEM_SZ);

    // ---- prep: fp16 (+permuted) operand copies
    roundperm_h<<<(int)(((long long)MB * D0 + 255) / 256), 256>>>(x, xr, (long long)MB * D0);
    roundperm_h<<<(int)(((long long)D1 * D0 + 255) / 256), 256>>>(W0, w0r, (long long)D1 * D0);
    roundperm_h<<<(int)(((long long)D2 * D1 + 255) / 256), 256>>>(W1, w1r, (long long)D2 * D1);
    roundperm_h<<<(int)(((long long)D3 * D2 + 255) / 256), 256>>>(W2, w2r, (long long)D3 * D2);
    transpose_rp_h<<<dim3(D0 / 32, D1 / 32), dim3(32, 8)>>>(W0, wt0, D1, D0);
    transpose_rp_h<<<dim3(D1 / 32, D2 / 32), dim3(32, 8)>>>(W1, wt1, D2, D1);
    transpose_rp_h<<<dim3(D2 / 32, D3 / 32), dim3(32, 8)>>>(W2, wt2, D3, D2);

    // ---- feedforward init: r_{i+1} = tanh(r_i @ W_i^T + b_i)
    tc_gemm<0><<<ggrid(D1), 256, SMEM_SZ>>>(xr,  w0r, b0, r1, r1r, D1, D0);
    tc_gemm<0><<<ggrid(D2), 256, SMEM_SZ>>>(r1r, w1r, b1, r2, r2r, D2, D1);
    tc_gemm<0><<<ggrid(D3), 256, SMEM_SZ>>>(r2r, w2r, b2, r3, r3r, D3, D2);

    // ---- fused phase descriptors (largest K first)
    Sub se1 = { r2r, wt1, r1, e1, e1r, D1, D2 };   // 16 tiles, K=2048
    Sub se0 = { r1r, wt0, x,  e0, e0r, D0, D1 };   // 8 tiles,  K=2048
    Sub se2 = { r3r, wt2, r2, e2, e2r, D2, D3 };   // 16 tiles, K=512
    Sub su2 = { e1r, w1r, e2, r2, r2r, D2, D1 };   // 16 tiles, K=2048
    Sub su3 = { e2r, w2r, r3, r3, r3r, D3, D2 };   // 4 tiles,  K=2048
    Sub su1 = { e0r, w0r, e1, r1, r1r, D1, D0 };   // 16 tiles, K=1024

    const dim3 gerr(16 + 8 + 16, MB / 128);
    const dim3 gupd(16 + 4 + 16, MB / 128);

    // ---- 20 PC inference steps: 2 launches per step
    for (int s = 0; s < NSTEPS; s++) {
        tc_gemm3<1><<<gerr, 256, SMEM_SZ>>>(se1, se0, se2, 16, 24);
        tc_gemm3<2><<<gupd, 256, SMEM_SZ>>>(su2, su3, su1, 16, 20);
    }

    // ---- final errors (fused)
    tc_gemm3<1><<<gerr, 256, SMEM_SZ>>>(se1, se0, se2, 16, 24);

    // ---- output r3
    const int n_r3 = MB * D3;
    copy_k<<<(n_r3 / 4 + 255) / 256, 256>>>(r3, out, n_r3 / 4);

    // ---- total_error = 0.5 * (|e0|^2 + |e1|^2 + |e2|^2 + |r3|^2)
    sumsq_partial<<<1024, 256>>>(e0, (long long)MB * D0, part + 0);
    sumsq_partial<<<1024, 256>>>(e1, (long long)MB * D1, part + 1024);
    sumsq_partial<<<1024, 256>>>(e2, (long long)MB * D2, part + 2048);
    sumsq_partial<<<1024, 256>>>(r3, (long long)MB * D3, part + 3072);
    finalize_k<<<1, 256>>>(part, 4096, out + (out_size - 1));
}

// round 11
// speedup vs baseline: 2.4254x; 1.0189x over previous
#include <cuda_runtime.h>
#include <cuda_fp16.h>
#include <cstdint>
#include <math.h>

// ---------------------------------------------------------------------------
// PcLinearBlock: ARCH=(1024,2048,2048,512), BATCH=4096, STEPS=20, LR=0.1
// fp16 mma.sync m16n8k16 + ldmatrix.x4 fragment loads, fp32 accumulate.
// 128x128x64 tile, cp.async 3-stage single-sync pipeline, full XOR swizzle
// (16B chunk ^= row&7) -> conflict-free ldmatrix. Plain row-major fp16
// operand shadows; exact fp32 state carries epilogues/reductions/output.
// Error/update phases fused into single launches via blockIdx routing.
// ---------------------------------------------------------------------------

#define MB 4096
#define D0 1024
#define D1 2048
#define D2 2048
#define D3 512
#define NSTEPS 20
#define LRC 0.1f

// ---- exact fp32 state ----
__device__ __align__(128) float g_r1[(size_t)MB * D1];
__device__ __align__(128) float g_r2[(size_t)MB * D2];
__device__ __align__(128) float g_r3[(size_t)MB * D3];
__device__ __align__(128) float g_e0[(size_t)MB * D0];
__device__ __align__(128) float g_e1[(size_t)MB * D1];
__device__ __align__(128) float g_e2[(size_t)MB * D2];
// ---- fp16-rounded row-major GEMM operand shadows ----
__device__ __align__(128) __half g_xr [(size_t)MB * D0];
__device__ __align__(128) __half g_r1r[(size_t)MB * D1];
__device__ __align__(128) __half g_r2r[(size_t)MB * D2];
__device__ __align__(128) __half g_r3r[(size_t)MB * D3];
__device__ __align__(128) __half g_e0r[(size_t)MB * D0];
__device__ __align__(128) __half g_e1r[(size_t)MB * D1];
__device__ __align__(128) __half g_e2r[(size_t)MB * D2];
__device__ __align__(128) __half g_W0r[(size_t)D1 * D0];
__device__ __align__(128) __half g_W1r[(size_t)D2 * D1];
__device__ __align__(128) __half g_W2r[(size_t)D3 * D2];
__device__ __align__(128) __half g_Wt0[(size_t)D0 * D1];
__device__ __align__(128) __half g_Wt1[(size_t)D1 * D2];
__device__ __align__(128) __half g_Wt2[(size_t)D2 * D3];
__device__ float g_part[4096];

// ---------------------------------------------------------------------------
// helpers
// ---------------------------------------------------------------------------
__device__ __forceinline__ uint32_t s2u(const void* p) {
    uint32_t a;
    asm("{ .reg .u64 t; cvta.to.shared.u64 t, %1; cvt.u32.u64 %0, t; }"
        : "=r"(a) : "l"(p));
    return a;
}
__device__ __forceinline__ void cp16(uint32_t dst, const void* src) {
    asm volatile("cp.async.cg.shared.global [%0], [%1], 16;"
                 :: "r"(dst), "l"(src));
}
__device__ __forceinline__ void ldm4(uint32_t* r, uint32_t addr) {
    asm volatile(
        "ldmatrix.sync.aligned.m8n8.x4.shared.b16 {%0,%1,%2,%3}, [%4];"
        : "=r"(r[0]), "=r"(r[1]), "=r"(r[2]), "=r"(r[3]) : "r"(addr));
}
__device__ __forceinline__ void mma16(float* c, const uint32_t* a,
                                      uint32_t b0, uint32_t b1) {
    asm volatile(
        "mma.sync.aligned.m16n8k16.row.col.f32.f16.f16.f32 "
        "{%0,%1,%2,%3}, {%4,%5,%6,%7}, {%8,%9}, {%0,%1,%2,%3};"
        : "+f"(c[0]), "+f"(c[1]), "+f"(c[2]), "+f"(c[3])
        : "r"(a[0]), "r"(a[1]), "r"(a[2]), "r"(a[3]), "r"(b0), "r"(b1));
}
__device__ __forceinline__ float fast_tanh(float x) {
    float e = __expf(2.0f * x);
    return 1.0f - 2.0f / (e + 1.0f);
}

// ---------------------------------------------------------------------------
// GEMM body:  C[m,n] = sum_k A[m,k]*B[n,k]   (fp16 row-major operands)
// 128x128x64 tile, 256 thr, 3-stage cp.async, ONE __syncthreads per chunk.
// ldmatrix.x4 fragment loads; swizzle: 16B chunk ^= (row & 7).
// EPI 0: D = tanh(acc + X[n]);  EPI 1: D = X - tanh(acc);
// EPI 2: D += LR*(acc - X).   Writes exact fp32 D and fp16 shadow Dr.
// ---------------------------------------------------------------------------
#define STG_B   32768            // A 16KB + B 16KB (128 rows x 128B each)
#define SMEM_SZ (3 * STG_B)

template <int EPI>
__device__ __forceinline__ void gemm_body(
    const __half* __restrict__ A, const __half* __restrict__ B,
    const float* __restrict__ X, float* __restrict__ D,
    __half* __restrict__ Dr, int N, int K, int bm, int bn, char* smem)
{
    const uint32_t sb = s2u(smem);
    const int tid = threadIdx.x;
    const int wid = tid >> 5, lane = tid & 31;
    const int gid = lane >> 2, tig = lane & 3;
    const int warp_m = wid & 1;
    const int warp_n = wid >> 1;

    // global->smem: thread t copies 64B of row t/2 (16B chunks, swizzled)
    const int ar = tid >> 1;
    const int half = tid & 1;
    const __half* gA = A + (size_t)(bm + ar) * K + half * 32;
    const __half* gB = B + (size_t)(bn + ar) * K + half * 32;
    uint32_t sw[4];
#pragma unroll
    for (int i = 0; i < 4; i++) {
        int cc = half * 4 + i;
        sw[i] = (uint32_t)(ar * 128 + ((cc ^ (ar & 7)) * 16));
    }

    const int KT = K >> 6;            // 64 fp16 per chunk = 128B row

    // ---- prologue: stages 0,1
#pragma unroll
    for (int kt = 0; kt < 2; kt++) {
        uint32_t base = sb + kt * STG_B;
        const __half* pa = gA + kt * 64;
        const __half* pb = gB + kt * 64;
#pragma unroll
        for (int i = 0; i < 4; i++) cp16(base + sw[i], pa + i * 8);
#pragma unroll
        for (int i = 0; i < 4; i++) cp16(base + 16384 + sw[i], pb + i * 8);
        asm volatile("cp.async.commit_group;" ::: "memory");
    }

    float acc[4][4][4];
#pragma unroll
    for (int mi = 0; mi < 4; mi++)
#pragma unroll
        for (int ni = 0; ni < 4; ni++)
#pragma unroll
            for (int r = 0; r < 4; r++) acc[mi][ni][r] = 0.f;

    // ldmatrix per-lane addressing:
    //   lanes 0-7:  rows 0-7,  k-lo | lanes 8-15: rows 8-15, k-lo
    //   lanes 16-23: rows 0-7, k-hi | lanes 24-31: rows 8-15, k-hi
    const int mrow = lane & 15;       // row within 16-row fragment
    const int khi  = lane >> 4;       // 0 = k0-7 chunk, 1 = k8-15 chunk
    const int rx   = mrow & 7;        // swizzle key (row & 7)
    const uint32_t arow0 = (uint32_t)((warp_m * 64 + mrow) * 128);
    const uint32_t brow0 = (uint32_t)((warp_n * 32 + mrow) * 128);

    // ---- mainloop: one barrier per 64-k chunk
    for (int kt = 0; kt < KT; kt++) {
        asm volatile("cp.async.wait_group 1;" ::: "memory");
        __syncthreads();
        const int kn = kt + 2;
        if (kn < KT) {
            uint32_t base = sb + (kn % 3) * STG_B;
            const __half* pa = gA + kn * 64;
            const __half* pb = gB + kn * 64;
#pragma unroll
            for (int i = 0; i < 4; i++) cp16(base + sw[i], pa + i * 8);
#pragma unroll
            for (int i = 0; i < 4; i++) cp16(base + 16384 + sw[i], pb + i * 8);
        }
        asm volatile("cp.async.commit_group;" ::: "memory");

        const uint32_t sA = sb + (kt % 3) * STG_B;
        const uint32_t sB = sA + 16384;

#pragma unroll
        for (int ks = 0; ks < 4; ks++) {            // 4 x k16 per chunk
            const uint32_t cb = (uint32_t)(((ks * 2 + khi) ^ rx) * 16);
            uint32_t a[4][4], b[2][4];
#pragma unroll
            for (int mi = 0; mi < 4; mi++)
                ldm4(a[mi], sA + arow0 + (uint32_t)(mi * 16 * 128) + cb);
#pragma unroll
            for (int nj = 0; nj < 2; nj++)
                ldm4(b[nj], sB + brow0 + (uint32_t)(nj * 16 * 128) + cb);
#pragma unroll
            for (int mi = 0; mi < 4; mi++)
#pragma unroll
                for (int ni = 0; ni < 4; ni++)
                    mma16(acc[mi][ni], a[mi],
                          b[ni >> 1][ni & 1], b[ni >> 1][(ni & 1) + 2]);
        }
    }

    // ---- fused epilogue: exact fp32 store + fp16 shadow
#pragma unroll
    for (int mi = 0; mi < 4; mi++) {
        const int gm = bm + warp_m * 64 + mi * 16 + gid;
#pragma unroll
        for (int ni = 0; ni < 4; ni++) {
            const int gn = bn + warp_n * 32 + ni * 8 + 2 * tig;   // even
            const size_t i0 = (size_t)gm * N + gn;
            const size_t i1 = i0 + (size_t)8 * N;
            const float* c = acc[mi][ni];
            float2 o0, o1;
            if (EPI == 0) {
                float b0v = X[gn], b1v = X[gn + 1];
                o0.x = fast_tanh(c[0] + b0v);
                o0.y = fast_tanh(c[1] + b1v);
                o1.x = fast_tanh(c[2] + b0v);
                o1.y = fast_tanh(c[3] + b1v);
            } else if (EPI == 1) {
                float2 x0 = *reinterpret_cast<const float2*>(&X[i0]);
                float2 x1 = *reinterpret_cast<const float2*>(&X[i1]);
                o0.x = x0.x - fast_tanh(c[0]);
                o0.y = x0.y - fast_tanh(c[1]);
                o1.x = x1.x - fast_tanh(c[2]);
                o1.y = x1.y - fast_tanh(c[3]);
            } else {
                float2 x0 = *reinterpret_cast<const float2*>(&X[i0]);
                float2 x1 = *reinterpret_cast<const float2*>(&X[i1]);
                float2 d0 = *reinterpret_cast<const float2*>(&D[i0]);
                float2 d1 = *reinterpret_cast<const float2*>(&D[i1]);
                o0.x = d0.x + LRC * (c[0] - x0.x);
                o0.y = d0.y + LRC * (c[1] - x0.y);
                o1.x = d1.x + LRC * (c[2] - x1.x);
                o1.y = d1.y + LRC * (c[3] - x1.y);
            }
            *reinterpret_cast<float2*>(&D[i0]) = o0;
            *reinterpret_cast<float2*>(&D[i1]) = o1;
            *reinterpret_cast<__half2*>(&Dr[i0]) =
                __halves2half2(__float2half_rn(o0.x), __float2half_rn(o0.y));
            *reinterpret_cast<__half2*>(&Dr[i1]) =
                __halves2half2(__float2half_rn(o1.x), __float2half_rn(o1.y));
        }
    }
}

// ---- single-GEMM kernel (feedforward) ----
template <int EPI>
__global__ void __launch_bounds__(256, 2)
tc_gemm(const __half* __restrict__ A, const __half* __restrict__ B,
        const float* __restrict__ X, float* __restrict__ D,
        __half* __restrict__ Dr, int N, int K)
{
    extern __shared__ char smem[];
    gemm_body<EPI>(A, B, X, D, Dr, N, K,
                   blockIdx.y * 128, blockIdx.x * 128, smem);
}

// ---- fused 3-GEMM kernel (error / update phases) ----
struct Sub {
    const __half* A; const __half* B; const float* X;
    float* D; __half* Dr; int N; int K;
};

template <int EPI>
__global__ void __launch_bounds__(256, 2)
tc_gemm3(Sub s0, Sub s1, Sub s2, int t0, int t1)
{
    extern __shared__ char smem[];
    const int bx = blockIdx.x;
    const __half *A, *B; const float* X; float* D; __half* Dr; int N, K, bn;
    if (bx < t0)      { A=s0.A; B=s0.B; X=s0.X; D=s0.D; Dr=s0.Dr;
                        N=s0.N; K=s0.K; bn = bx * 128; }
    else if (bx < t1) { A=s1.A; B=s1.B; X=s1.X; D=s1.D; Dr=s1.Dr;
                        N=s1.N; K=s1.K; bn = (bx - t0) * 128; }
    else              { A=s2.A; B=s2.B; X=s2.X; D=s2.D; Dr=s2.Dr;
                        N=s2.N; K=s2.K; bn = (bx - t1) * 128; }
    gemm_body<EPI>(A, B, X, D, Dr, N, K, blockIdx.y * 128, bn, smem);
}

// ---------------------------------------------------------------------------
// prep kernels: fp32 -> fp16 (and transpose for Wt); plain row-major
// ---------------------------------------------------------------------------
__global__ void round_h(const float* __restrict__ src,
                        __half* __restrict__ dst, long long n)
{
    long long i = (long long)blockIdx.x * blockDim.x + threadIdx.x;
    if (i * 2 < n) {
        float2 v = reinterpret_cast<const float2*>(src)[i];
        reinterpret_cast<__half2*>(dst)[i] =
            __halves2half2(__float2half_rn(v.x), __float2half_rn(v.y));
    }
}

__global__ void transpose_h(const float* __restrict__ src,
                            __half* __restrict__ dst, int R, int C)
{
    __shared__ float t[32][33];
    int bx = blockIdx.x * 32, by = blockIdx.y * 32;
    int x = bx + threadIdx.x;
#pragma unroll
    for (int i = 0; i < 32; i += 8)
        t[threadIdx.y + i][threadIdx.x] =
            src[(size_t)(by + threadIdx.y + i) * C + x];
    __syncthreads();
    int xo = by + threadIdx.x;
#pragma unroll
    for (int i = 0; i < 32; i += 8)
        dst[(size_t)(bx + threadIdx.y + i) * R + xo] =
            __float2half_rn(t[threadIdx.x][threadIdx.y + i]);
}

// ---------------------------------------------------------------------------
// output copy + deterministic two-stage sum-of-squares
// ---------------------------------------------------------------------------
__global__ void copy_k(const float* __restrict__ s, float* __restrict__ d,
                       int n4)
{
    int i = blockIdx.x * blockDim.x + threadIdx.x;
    if (i < n4)
        reinterpret_cast<float4*>(d)[i] =
            reinterpret_cast<const float4*>(s)[i];
}

__global__ void sumsq_partial(const float* __restrict__ x, long long n,
                              float* __restrict__ part)
{
    float s = 0.f;
    long long stride = (long long)gridDim.x * blockDim.x;
    for (long long i = (long long)blockIdx.x * blockDim.x + threadIdx.x;
         i < n; i += stride) {
        float v = x[i];
        s = fmaf(v, v, s);
    }
    __shared__ float sh[256];
    sh[threadIdx.x] = s;
    __syncthreads();
    for (int o = 128; o > 0; o >>= 1) {
        if (threadIdx.x < o) sh[threadIdx.x] += sh[threadIdx.x + o];
        __syncthreads();
    }
    if (threadIdx.x == 0) part[blockIdx.x] = sh[0];
}

__global__ void finalize_k(const float* __restrict__ part, int n,
                           float* __restrict__ out)
{
    float s = 0.f;
    for (int i = threadIdx.x; i < n; i += 256) s += part[i];
    __shared__ float sh[256];
    sh[threadIdx.x] = s;
    __syncthreads();
    for (int o = 128; o > 0; o >>= 1) {
        if (threadIdx.x < o) sh[threadIdx.x] += sh[threadIdx.x + o];
        __syncthreads();
    }
    if (threadIdx.x == 0) out[0] = 0.5f * sh[0];
}

// ---------------------------------------------------------------------------
// Launch
// ---------------------------------------------------------------------------
static inline dim3 ggrid(int N) { return dim3(N / 128, MB / 128); }

extern "C" void kernel_launch(void* const* d_in, const int* in_sizes, int n_in,
                              void* d_out, int out_size)
{
    const float* x  = (const float*)d_in[0];
    const float* W0 = (const float*)d_in[1];
    const float* b0 = (const float*)d_in[2];
    const float* W1 = (const float*)d_in[3];
    const float* b1 = (const float*)d_in[4];
    const float* W2 = (const float*)d_in[5];
    const float* b2 = (const float*)d_in[6];
    float* out = (float*)d_out;

    float *r1, *r2, *r3, *e0, *e1, *e2, *part;
    __half *xr, *r1r, *r2r, *r3r, *e0r, *e1r, *e2r;
    __half *w0r, *w1r, *w2r, *wt0, *wt1, *wt2;
    cudaGetSymbolAddress((void**)&r1,  g_r1);
    cudaGetSymbolAddress((void**)&r2,  g_r2);
    cudaGetSymbolAddress((void**)&r3,  g_r3);
    cudaGetSymbolAddress((void**)&e0,  g_e0);
    cudaGetSymbolAddress((void**)&e1,  g_e1);
    cudaGetSymbolAddress((void**)&e2,  g_e2);
    cudaGetSymbolAddress((void**)&xr,  g_xr);
    cudaGetSymbolAddress((void**)&r1r, g_r1r);
    cudaGetSymbolAddress((void**)&r2r, g_r2r);
    cudaGetSymbolAddress((void**)&r3r, g_r3r);
    cudaGetSymbolAddress((void**)&e0r, g_e0r);
    cudaGetSymbolAddress((void**)&e1r, g_e1r);
    cudaGetSymbolAddress((void**)&e2r, g_e2r);
    cudaGetSymbolAddress((void**)&w0r, g_W0r);
    cudaGetSymbolAddress((void**)&w1r, g_W1r);
    cudaGetSymbolAddress((void**)&w2r, g_W2r);
    cudaGetSymbolAddress((void**)&wt0, g_Wt0);
    cudaGetSymbolAddress((void**)&wt1, g_Wt1);
    cudaGetSymbolAddress((void**)&wt2, g_Wt2);
    cudaGetSymbolAddress((void**)&part, g_part);

    cudaFuncSetAttribute(tc_gemm<0>,  cudaFuncAttributeMaxDynamicSharedMemorySize, SMEM_SZ);
    cudaFuncSetAttribute(tc_gemm3<1>, cudaFuncAttributeMaxDynamicSharedMemorySize, SMEM_SZ);
    cudaFuncSetAttribute(tc_gemm3<2>, cudaFuncAttributeMaxDynamicSharedMemorySize, SMEM_SZ);

    // ---- prep: fp16 operand copies (row-major)
    round_h<<<(int)(((long long)MB * D0 / 2 + 255) / 256), 256>>>(x, xr, (long long)MB * D0);
    round_h<<<(int)(((long long)D1 * D0 / 2 + 255) / 256), 256>>>(W0, w0r, (long long)D1 * D0);
    round_h<<<(int)(((long long)D2 * D1 / 2 + 255) / 256), 256>>>(W1, w1r, (long long)D2 * D1);
    round_h<<<(int)(((long long)D3 * D2 / 2 + 255) / 256), 256>>>(W2, w2r, (long long)D3 * D2);
    transpose_h<<<dim3(D0 / 32, D1 / 32), dim3(32, 8)>>>(W0, wt0, D1, D0);
    transpose_h<<<dim3(D1 / 32, D2 / 32), dim3(32, 8)>>>(W1, wt1, D2, D1);
    transpose_h<<<dim3(D2 / 32, D3 / 32), dim3(32, 8)>>>(W2, wt2, D3, D2);

    // ---- feedforward init: r_{i+1} = tanh(r_i @ W_i^T + b_i)
    tc_gemm<0><<<ggrid(D1), 256, SMEM_SZ>>>(xr,  w0r, b0, r1, r1r, D1, D0);
    tc_gemm<0><<<ggrid(D2), 256, SMEM_SZ>>>(r1r, w1r, b1, r2, r2r, D2, D1);
    tc_gemm<0><<<ggrid(D3), 256, SMEM_SZ>>>(r2r, w2r, b2, r3, r3r, D3, D2);

    // ---- fused phase descriptors (largest K first)
    Sub se1 = { r2r, wt1, r1, e1, e1r, D1, D2 };   // 16 tiles, K=2048
    Sub se0 = { r1r, wt0, x,  e0, e0r, D0, D1 };   // 8 tiles,  K=2048
    Sub se2 = { r3r, wt2, r2, e2, e2r, D2, D3 };   // 16 tiles, K=512
    Sub su2 = { e1r, w1r, e2, r2, r2r, D2, D1 };   // 16 tiles, K=2048
    Sub su3 = { e2r, w2r, r3, r3, r3r, D3, D2 };   // 4 tiles,  K=2048
    Sub su1 = { e0r, w0r, e1, r1, r1r, D1, D0 };   // 16 tiles, K=1024

    const dim3 gerr(16 + 8 + 16, MB / 128);
    const dim3 gupd(16 + 4 + 16, MB / 128);

    // ---- 20 PC inference steps: 2 launches per step
    for (int s = 0; s < NSTEPS; s++) {
        tc_gemm3<1><<<gerr, 256, SMEM_SZ>>>(se1, se0, se2, 16, 24);
        tc_gemm3<2><<<gupd, 256, SMEM_SZ>>>(su2, su3, su1, 16, 20);
    }

    // ---- final errors (fused)
    tc_gemm3<1><<<gerr, 256, SMEM_SZ>>>(se1, se0, se2, 16, 24);

    // ---- output r3
    const int n_r3 = MB * D3;
    copy_k<<<(n_r3 / 4 + 255) / 256, 256>>>(r3, out, n_r3 / 4);

    // ---- total_error = 0.5 * (|e0|^2 + |e1|^2 + |e2|^2 + |r3|^2)
    sumsq_partial<<<1024, 256>>>(e0, (long long)MB * D0, part + 0);
    sumsq_partial<<<1024, 256>>>(e1, (long long)MB * D1, part + 1024);
    sumsq_partial<<<1024, 256>>>(e2, (long long)MB * D2, part + 2048);
    sumsq_partial<<<1024, 256>>>(r3, (long long)MB * D3, part + 3072);
    finalize_k<<<1, 256>>>(part, 4096, out + (out_size - 1));
}

// round 12
// speedup vs baseline: 2.4274x; 1.0008x over previous
#include <cuda_runtime.h>
#include <cuda_fp16.h>
#include <cstdint>
#include <math.h>

// ---------------------------------------------------------------------------
// PcLinearBlock: ARCH=(1024,2048,2048,512), BATCH=4096, STEPS=20, LR=0.1
// fp16 mma.sync m16n8k16 + ldmatrix.x4 fragment loads, fp32 accumulate.
// 128x128x64 tile, cp.async 3-stage single-sync pipeline, full XOR swizzle
// (16B chunk ^= row&7) -> conflict-free ldmatrix. Plain row-major fp16
// operand shadows; exact fp32 state carries epilogues/reductions/output.
// Error/update phases fused into single launches via blockIdx routing.
// ---------------------------------------------------------------------------

#define MB 4096
#define D0 1024
#define D1 2048
#define D2 2048
#define D3 512
#define NSTEPS 20
#define LRC 0.1f

// ---- exact fp32 state ----
__device__ __align__(128) float g_r1[(size_t)MB * D1];
__device__ __align__(128) float g_r2[(size_t)MB * D2];
__device__ __align__(128) float g_r3[(size_t)MB * D3];
__device__ __align__(128) float g_e0[(size_t)MB * D0];
__device__ __align__(128) float g_e1[(size_t)MB * D1];
__device__ __align__(128) float g_e2[(size_t)MB * D2];
// ---- fp16-rounded row-major GEMM operand shadows ----
__device__ __align__(128) __half g_xr [(size_t)MB * D0];
__device__ __align__(128) __half g_r1r[(size_t)MB * D1];
__device__ __align__(128) __half g_r2r[(size_t)MB * D2];
__device__ __align__(128) __half g_r3r[(size_t)MB * D3];
__device__ __align__(128) __half g_e0r[(size_t)MB * D0];
__device__ __align__(128) __half g_e1r[(size_t)MB * D1];
__device__ __align__(128) __half g_e2r[(size_t)MB * D2];
__device__ __align__(128) __half g_W0r[(size_t)D1 * D0];
__device__ __align__(128) __half g_W1r[(size_t)D2 * D1];
__device__ __align__(128) __half g_W2r[(size_t)D3 * D2];
__device__ __align__(128) __half g_Wt0[(size_t)D0 * D1];
__device__ __align__(128) __half g_Wt1[(size_t)D1 * D2];
__device__ __align__(128) __half g_Wt2[(size_t)D2 * D3];
__device__ float g_part[4096];

// ---------------------------------------------------------------------------
// helpers
// ---------------------------------------------------------------------------
__device__ __forceinline__ uint32_t s2u(const void* p) {
    uint32_t a;
    asm("{ .reg .u64 t; cvta.to.shared.u64 t, %1; cvt.u32.u64 %0, t; }"
        : "=r"(a) : "l"(p));
    return a;
}
__device__ __forceinline__ void cp16(uint32_t dst, const void* src) {
    asm volatile("cp.async.cg.shared.global [%0], [%1], 16;"
                 :: "r"(dst), "l"(src));
}
__device__ __forceinline__ void ldm4(uint32_t* r, uint32_t addr) {
    asm volatile(
        "ldmatrix.sync.aligned.m8n8.x4.shared.b16 {%0,%1,%2,%3}, [%4];"
        : "=r"(r[0]), "=r"(r[1]), "=r"(r[2]), "=r"(r[3]) : "r"(addr));
}
__device__ __forceinline__ void mma16(float* c, const uint32_t* a,
                                      uint32_t b0, uint32_t b1) {
    asm volatile(
        "mma.sync.aligned.m16n8k16.row.col.f32.f16.f16.f32 "
        "{%0,%1,%2,%3}, {%4,%5,%6,%7}, {%8,%9}, {%0,%1,%2,%3};"
        : "+f"(c[0]), "+f"(c[1]), "+f"(c[2]), "+f"(c[3])
        : "r"(a[0]), "r"(a[1]), "r"(a[2]), "r"(a[3]), "r"(b0), "r"(b1));
}
__device__ __forceinline__ float fast_tanh(float x) {
    float e = __expf(2.0f * x);
    return 1.0f - 2.0f / (e + 1.0f);
}

// ---------------------------------------------------------------------------
// GEMM body:  C[m,n] = sum_k A[m,k]*B[n,k]   (fp16 row-major operands)
// 128x128x64 tile, 256 thr, 3-stage cp.async, ONE __syncthreads per chunk.
// ldmatrix.x4 fragment loads; swizzle: 16B chunk ^= (row & 7).
// EPI 0: D = tanh(acc + X[n]);  EPI 1: D = X - tanh(acc);
// EPI 2: D += LR*(acc - X).   Writes exact fp32 D and fp16 shadow Dr.
// ---------------------------------------------------------------------------
#define STG_B   32768            // A 16KB + B 16KB (128 rows x 128B each)
#define SMEM_SZ (3 * STG_B)

template <int EPI>
__device__ __forceinline__ void gemm_body(
    const __half* __restrict__ A, const __half* __restrict__ B,
    const float* __restrict__ X, float* __restrict__ D,
    __half* __restrict__ Dr, int N, int K, int bm, int bn, char* smem)
{
    const uint32_t sb = s2u(smem);
    const int tid = threadIdx.x;
    const int wid = tid >> 5, lane = tid & 31;
    const int gid = lane >> 2, tig = lane & 3;
    const int warp_m = wid & 1;
    const int warp_n = wid >> 1;

    // global->smem: thread t copies 64B of row t/2 (16B chunks, swizzled)
    const int ar = tid >> 1;
    const int half = tid & 1;
    const __half* gA = A + (size_t)(bm + ar) * K + half * 32;
    const __half* gB = B + (size_t)(bn + ar) * K + half * 32;
    uint32_t sw[4];
#pragma unroll
    for (int i = 0; i < 4; i++) {
        int cc = half * 4 + i;
        sw[i] = (uint32_t)(ar * 128 + ((cc ^ (ar & 7)) * 16));
    }

    const int KT = K >> 6;            // 64 fp16 per chunk = 128B row

    // ---- prologue: stages 0,1
#pragma unroll
    for (int kt = 0; kt < 2; kt++) {
        uint32_t base = sb + kt * STG_B;
        const __half* pa = gA + kt * 64;
        const __half* pb = gB + kt * 64;
#pragma unroll
        for (int i = 0; i < 4; i++) cp16(base + sw[i], pa + i * 8);
#pragma unroll
        for (int i = 0; i < 4; i++) cp16(base + 16384 + sw[i], pb + i * 8);
        asm volatile("cp.async.commit_group;" ::: "memory");
    }

    float acc[4][4][4];
#pragma unroll
    for (int mi = 0; mi < 4; mi++)
#pragma unroll
        for (int ni = 0; ni < 4; ni++)
#pragma unroll
            for (int r = 0; r < 4; r++) acc[mi][ni][r] = 0.f;

    // ldmatrix per-lane addressing:
    //   lanes 0-7:  rows 0-7,  k-lo | lanes 8-15: rows 8-15, k-lo
    //   lanes 16-23: rows 0-7, k-hi | lanes 24-31: rows 8-15, k-hi
    const int mrow = lane & 15;       // row within 16-row fragment
    const int khi  = lane >> 4;       // 0 = k0-7 chunk, 1 = k8-15 chunk
    const int rx   = mrow & 7;        // swizzle key (row & 7)
    const uint32_t arow0 = (uint32_t)((warp_m * 64 + mrow) * 128);
    const uint32_t brow0 = (uint32_t)((warp_n * 32 + mrow) * 128);

    // ---- mainloop: one barrier per 64-k chunk
    for (int kt = 0; kt < KT; kt++) {
        asm volatile("cp.async.wait_group 1;" ::: "memory");
        __syncthreads();
        const int kn = kt + 2;
        if (kn < KT) {
            uint32_t base = sb + (kn % 3) * STG_B;
            const __half* pa = gA + kn * 64;
            const __half* pb = gB + kn * 64;
#pragma unroll
            for (int i = 0; i < 4; i++) cp16(base + sw[i], pa + i * 8);
#pragma unroll
            for (int i = 0; i < 4; i++) cp16(base + 16384 + sw[i], pb + i * 8);
        }
        asm volatile("cp.async.commit_group;" ::: "memory");

        const uint32_t sA = sb + (kt % 3) * STG_B;
        const uint32_t sB = sA + 16384;

#pragma unroll
        for (int ks = 0; ks < 4; ks++) {            // 4 x k16 per chunk
            const uint32_t cb = (uint32_t)(((ks * 2 + khi) ^ rx) * 16);
            uint32_t a[4][4], b[2][4];
#pragma unroll
            for (int mi = 0; mi < 4; mi++)
                ldm4(a[mi], sA + arow0 + (uint32_t)(mi * 16 * 128) + cb);
#pragma unroll
            for (int nj = 0; nj < 2; nj++)
                ldm4(b[nj], sB + brow0 + (uint32_t)(nj * 16 * 128) + cb);
#pragma unroll
            for (int mi = 0; mi < 4; mi++)
#pragma unroll
                for (int ni = 0; ni < 4; ni++)
                    mma16(acc[mi][ni], a[mi],
                          b[ni >> 1][ni & 1], b[ni >> 1][(ni & 1) + 2]);
        }
    }

    // ---- fused epilogue: exact fp32 store + fp16 shadow
#pragma unroll
    for (int mi = 0; mi < 4; mi++) {
        const int gm = bm + warp_m * 64 + mi * 16 + gid;
#pragma unroll
        for (int ni = 0; ni < 4; ni++) {
            const int gn = bn + warp_n * 32 + ni * 8 + 2 * tig;   // even
            const size_t i0 = (size_t)gm * N + gn;
            const size_t i1 = i0 + (size_t)8 * N;
            const float* c = acc[mi][ni];
            float2 o0, o1;
            if (EPI == 0) {
                float b0v = X[gn], b1v = X[gn + 1];
                o0.x = fast_tanh(c[0] + b0v);
                o0.y = fast_tanh(c[1] + b1v);
                o1.x = fast_tanh(c[2] + b0v);
                o1.y = fast_tanh(c[3] + b1v);
            } else if (EPI == 1) {
                float2 x0 = *reinterpret_cast<const float2*>(&X[i0]);
                float2 x1 = *reinterpret_cast<const float2*>(&X[i1]);
                o0.x = x0.x - fast_tanh(c[0]);
                o0.y = x0.y - fast_tanh(c[1]);
                o1.x = x1.x - fast_tanh(c[2]);
                o1.y = x1.y - fast_tanh(c[3]);
            } else {
                float2 x0 = *reinterpret_cast<const float2*>(&X[i0]);
                float2 x1 = *reinterpret_cast<const float2*>(&X[i1]);
                float2 d0 = *reinterpret_cast<const float2*>(&D[i0]);
                float2 d1 = *reinterpret_cast<const float2*>(&D[i1]);
                o0.x = d0.x + LRC * (c[0] - x0.x);
                o0.y = d0.y + LRC * (c[1] - x0.y);
                o1.x = d1.x + LRC * (c[2] - x1.x);
                o1.y = d1.y + LRC * (c[3] - x1.y);
            }
            *reinterpret_cast<float2*>(&D[i0]) = o0;
            *reinterpret_cast<float2*>(&D[i1]) = o1;
            *reinterpret_cast<__half2*>(&Dr[i0]) =
                __halves2half2(__float2half_rn(o0.x), __float2half_rn(o0.y));
            *reinterpret_cast<__half2*>(&Dr[i1]) =
                __halves2half2(__float2half_rn(o1.x), __float2half_rn(o1.y));
        }
    }
}

// ---- single-GEMM kernel (feedforward) ----
template <int EPI>
__global__ void __launch_bounds__(256, 2)
tc_gemm(const __half* __restrict__ A, const __half* __restrict__ B,
        const float* __restrict__ X, float* __restrict__ D,
        __half* __restrict__ Dr, int N, int K)
{
    extern __shared__ char smem[];
    gemm_body<EPI>(A, B, X, D, Dr, N, K,
                   blockIdx.y * 128, blockIdx.x * 128, smem);
}

// ---- fused 3-GEMM kernel (error / update phases) ----
struct Sub {
    const __half* A; const __half* B; const float* X;
    float* D; __half* Dr; int N; int K;
};

template <int EPI>
__global__ void __launch_bounds__(256, 2)
tc_gemm3(Sub s0, Sub s1, Sub s2, int t0, int t1)
{
    extern __shared__ char smem[];
    const int bx = blockIdx.x;
    const __half *A, *B; const float* X; float* D; __half* Dr; int N, K, bn;
    if (bx < t0)      { A=s0.A; B=s0.B; X=s0.X; D=s0.D; Dr=s0.Dr;
                        N=s0.N; K=s0.K; bn = bx * 128; }
    else if (bx < t1) { A=s1.A; B=s1.B; X=s1.X; D=s1.D; Dr=s1.Dr;
                        N=s1.N; K=s1.K; bn = (bx - t0) * 128; }
    else              { A=s2.A; B=s2.B; X=s2.X; D=s2.D; Dr=s2.Dr;
                        N=s2.N; K=s2.K; bn = (bx - t1) * 128; }
    gemm_body<EPI>(A, B, X, D, Dr, N, K, blockIdx.y * 128, bn, smem);
}

// ---------------------------------------------------------------------------
// prep kernels: fp32 -> fp16 (and transpose for Wt); plain row-major
// ---------------------------------------------------------------------------
__global__ void round_h(const float* __restrict__ src,
                        __half* __restrict__ dst, long long n)
{
    long long i = (long long)blockIdx.x * blockDim.x + threadIdx.x;
    if (i * 2 < n) {
        float2 v = reinterpret_cast<const float2*>(src)[i];
        reinterpret_cast<__half2*>(dst)[i] =
            __halves2half2(__float2half_rn(v.x), __float2half_rn(v.y));
    }
}

__global__ void transpose_h(const float* __restrict__ src,
                            __half* __restrict__ dst, int R, int C)
{
    __shared__ float t[32][33];
    int bx = blockIdx.x * 32, by = blockIdx.y * 32;
    int x = bx + threadIdx.x;
#pragma unroll
    for (int i = 0; i < 32; i += 8)
        t[threadIdx.y + i][threadIdx.x] =
            src[(size_t)(by + threadIdx.y + i) * C + x];
    __syncthreads();
    int xo = by + threadIdx.x;
#pragma unroll
    for (int i = 0; i < 32; i += 8)
        dst[(size_t)(bx + threadIdx.y + i) * R + xo] =
            __float2half_rn(t[threadIdx.x][threadIdx.y + i]);
}

// ---------------------------------------------------------------------------
// output copy + deterministic two-stage sum-of-squares
// ---------------------------------------------------------------------------
__global__ void copy_k(const float* __restrict__ s, float* __restrict__ d,
                       int n4)
{
    int i = blockIdx.x * blockDim.x + threadIdx.x;
    if (i < n4)
        reinterpret_cast<float4*>(d)[i] =
            reinterpret_cast<const float4*>(s)[i];
}

__global__ void sumsq_partial(const float* __restrict__ x, long long n,
                              float* __restrict__ part)
{
    float s = 0.f;
    long long stride = (long long)gridDim.x * blockDim.x;
    for (long long i = (long long)blockIdx.x * blockDim.x + threadIdx.x;
         i < n; i += stride) {
        float v = x[i];
        s = fmaf(v, v, s);
    }
    __shared__ float sh[256];
    sh[threadIdx.x] = s;
    __syncthreads();
    for (int o = 128; o > 0; o >>= 1) {
        if (threadIdx.x < o) sh[threadIdx.x] += sh[threadIdx.x + o];
        __syncthreads();
    }
    if (threadIdx.x == 0) part[blockIdx.x] = sh[0];
}

__global__ void finalize_k(const float* __restrict__ part, int n,
                           float* __restrict__ out)
{
    float s = 0.f;
    for (int i = threadIdx.x; i < n; i += 256) s += part[i];
    __shared__ float sh[256];
    sh[threadIdx.x] = s;
    __syncthreads();
    for (int o = 128; o > 0; o >>= 1) {
        if (threadIdx.x < o) sh[threadIdx.x] += sh[threadIdx.x + o];
        __syncthreads();
    }
    if (threadIdx.x == 0) out[0] = 0.5f * sh[0];
}

// ---------------------------------------------------------------------------
// Launch
// ---------------------------------------------------------------------------
static inline dim3 ggrid(int N) { return dim3(N / 128, MB / 128); }

extern "C" void kernel_launch(void* const* d_in, const int* in_sizes, int n_in,
                              void* d_out, int out_size)
{
    const float* x  = (const float*)d_in[0];
    const float* W0 = (const float*)d_in[1];
    const float* b0 = (const float*)d_in[2];
    const float* W1 = (const float*)d_in[3];
    const float* b1 = (const float*)d_in[4];
    const float* W2 = (const float*)d_in[5];
    const float* b2 = (const float*)d_in[6];
    float* out = (float*)d_out;

    float *r1, *r2, *r3, *e0, *e1, *e2, *part;
    __half *xr, *r1r, *r2r, *r3r, *e0r, *e1r, *e2r;
    __half *w0r, *w1r, *w2r, *wt0, *wt1, *wt2;
    cudaGetSymbolAddress((void**)&r1,  g_r1);
    cudaGetSymbolAddress((void**)&r2,  g_r2);
    cudaGetSymbolAddress((void**)&r3,  g_r3);
    cudaGetSymbolAddress((void**)&e0,  g_e0);
    cudaGetSymbolAddress((void**)&e1,  g_e1);
    cudaGetSymbolAddress((void**)&e2,  g_e2);
    cudaGetSymbolAddress((void**)&xr,  g_xr);
    cudaGetSymbolAddress((void**)&r1r, g_r1r);
    cudaGetSymbolAddress((void**)&r2r, g_r2r);
    cudaGetSymbolAddress((void**)&r3r, g_r3r);
    cudaGetSymbolAddress((void**)&e0r, g_e0r);
    cudaGetSymbolAddress((void**)&e1r, g_e1r);
    cudaGetSymbolAddress((void**)&e2r, g_e2r);
    cudaGetSymbolAddress((void**)&w0r, g_W0r);
    cudaGetSymbolAddress((void**)&w1r, g_W1r);
    cudaGetSymbolAddress((void**)&w2r, g_W2r);
    cudaGetSymbolAddress((void**)&wt0, g_Wt0);
    cudaGetSymbolAddress((void**)&wt1, g_Wt1);
    cudaGetSymbolAddress((void**)&wt2, g_Wt2);
    cudaGetSymbolAddress((void**)&part, g_part);

    cudaFuncSetAttribute(tc_gemm<0>,  cudaFuncAttributeMaxDynamicSharedMemorySize, SMEM_SZ);
    cudaFuncSetAttribute(tc_gemm3<1>, cudaFuncAttributeMaxDynamicSharedMemorySize, SMEM_SZ);
    cudaFuncSetAttribute(tc_gemm3<2>, cudaFuncAttributeMaxDynamicSharedMemorySize, SMEM_SZ);

    // ---- prep: fp16 operand copies (row-major)
    round_h<<<(int)(((long long)MB * D0 / 2 + 255) / 256), 256>>>(x, xr, (long long)MB * D0);
    round_h<<<(int)(((long long)D1 * D0 / 2 + 255) / 256), 256>>>(W0, w0r, (long long)D1 * D0);
    round_h<<<(int)(((long long)D2 * D1 / 2 + 255) / 256), 256>>>(W1, w1r, (long long)D2 * D1);
    round_h<<<(int)(((long long)D3 * D2 / 2 + 255) / 256), 256>>>(W2, w2r, (long long)D3 * D2);
    transpose_h<<<dim3(D0 / 32, D1 / 32), dim3(32, 8)>>>(W0, wt0, D1, D0);
    transpose_h<<<dim3(D1 / 32, D2 / 32), dim3(32, 8)>>>(W1, wt1, D2, D1);
    transpose_h<<<dim3(D2 / 32, D3 / 32), dim3(32, 8)>>>(W2, wt2, D3, D2);

    // ---- feedforward init: r_{i+1} = tanh(r_i @ W_i^T + b_i)
    tc_gemm<0><<<ggrid(D1), 256, SMEM_SZ>>>(xr,  w0r, b0, r1, r1r, D1, D0);
    tc_gemm<0><<<ggrid(D2), 256, SMEM_SZ>>>(r1r, w1r, b1, r2, r2r, D2, D1);
    tc_gemm<0><<<ggrid(D3), 256, SMEM_SZ>>>(r2r, w2r, b2, r3, r3r, D3, D2);

    // ---- fused phase descriptors (largest K first)
    Sub se1 = { r2r, wt1, r1, e1, e1r, D1, D2 };   // 16 tiles, K=2048
    Sub se0 = { r1r, wt0, x,  e0, e0r, D0, D1 };   // 8 tiles,  K=2048
    Sub se2 = { r3r, wt2, r2, e2, e2r, D2, D3 };   // 16 tiles, K=512
    Sub su2 = { e1r, w1r, e2, r2, r2r, D2, D1 };   // 16 tiles, K=2048
    Sub su3 = { e2r, w2r, r3, r3, r3r, D3, D2 };   // 4 tiles,  K=2048
    Sub su1 = { e0r, w0r, e1, r1, r1r, D1, D0 };   // 16 tiles, K=1024

    const dim3 gerr(16 + 8 + 16, MB / 128);
    const dim3 gupd(16 + 4 + 16, MB / 128);

    // ---- 20 PC inference steps: 2 launches per step
    for (int s = 0; s < NSTEPS; s++) {
        tc_gemm3<1><<<gerr, 256, SMEM_SZ>>>(se1, se0, se2, 16, 24);
        tc_gemm3<2><<<gupd, 256, SMEM_SZ>>>(su2, su3, su1, 16, 20);
    }

    // ---- final errors (fused)
    tc_gemm3<1><<<gerr, 256, SMEM_SZ>>>(se1, se0, se2, 16, 24);

    // ---- output r3
    const int n_r3 = MB * D3;
    copy_k<<<(n_r3 / 4 + 255) / 256, 256>>>(r3, out, n_r3 / 4);

    // ---- total_error = 0.5 * (|e0|^2 + |e1|^2 + |e2|^2 + |r3|^2)
    sumsq_partial<<<1024, 256>>>(e0, (long long)MB * D0, part + 0);
    sumsq_partial<<<1024, 256>>>(e1, (long long)MB * D1, part + 1024);
    sumsq_partial<<<1024, 256>>>(e2, (long long)MB * D2, part + 2048);
    sumsq_partial<<<1024, 256>>>(r3, (long long)MB * D3, part + 3072);
    finalize_k<<<1, 256>>>(part, 4096, out + (out_size - 1));
}